// round 11
// baseline (speedup 1.0000x reference)
#include <cuda_runtime.h>
#include <cuda_bf16.h>
#include <math.h>
#include <stdint.h>

// ---------------------------------------------------------------------------
// GPT-2 transformer block. GEMMs + attention on mma.sync bf16 (hi/lo split).
// Attention: pre-split bf16 qkv, cp.async double-buffered tiles, FMA-pipe exp.
// B=2, T=2048, C=768, H=12, hd=64.  M = B*T = 4096.
// ---------------------------------------------------------------------------

#define M_ROWS 4096
#define C_DIM  768
#define C3_DIM 2304
#define C4_DIM 3072
#define N_HEAD 12
#define HD     64
#define T_SEQ  2048

// ---------------- scratch (device globals) ----------------
__device__ float g_x1 [M_ROWS * C_DIM];
__device__ __nv_bfloat16 g_qkvh[M_ROWS * C3_DIM], g_qkvl[M_ROWS * C3_DIM];
__device__ __nv_bfloat16 g_hh [M_ROWS * C_DIM],  g_hl [M_ROWS * C_DIM];
__device__ __nv_bfloat16 g_yh [M_ROWS * C_DIM],  g_yl [M_ROWS * C_DIM];
__device__ __nv_bfloat16 g_h2h[M_ROWS * C_DIM],  g_h2l[M_ROWS * C_DIM];
__device__ __nv_bfloat16 g_uh [M_ROWS * C4_DIM], g_ul [M_ROWS * C4_DIM];
__device__ __nv_bfloat16 g_wqh[C3_DIM * C_DIM],  g_wql[C3_DIM * C_DIM];
__device__ __nv_bfloat16 g_wph[C_DIM * C_DIM],   g_wpl[C_DIM * C_DIM];
__device__ __nv_bfloat16 g_wfh[C4_DIM * C_DIM],  g_wfl[C4_DIM * C_DIM];
__device__ __nv_bfloat16 g_wmh[C_DIM * C4_DIM],  g_wml[C_DIM * C4_DIM];

// ---------------- PTX helpers (base ISA only) ----------
__device__ __forceinline__ uint32_t smem_u32(const void* p) {
    uint32_t a;
    asm("{ .reg .u64 t; cvta.to.shared.u64 t, %1; cvt.u32.u64 %0, t; }"
        : "=r"(a) : "l"(p));
    return a;
}

#define CPA16(dst, src) \
    asm volatile("cp.async.cg.shared.global [%0], [%1], 16;" :: "r"(dst), "l"(src))
#define CP_COMMIT() asm volatile("cp.async.commit_group;" ::: "memory")
#define CP_WAIT1()  asm volatile("cp.async.wait_group 1;" ::: "memory")
#define CP_WAIT0()  asm volatile("cp.async.wait_group 0;" ::: "memory")

#define LDSM_X4(r, addr)                                                       \
    asm volatile("ldmatrix.sync.aligned.m8n8.x4.shared.b16 {%0,%1,%2,%3}, [%4];" \
        : "=r"((r)[0]), "=r"((r)[1]), "=r"((r)[2]), "=r"((r)[3]) : "r"(addr))

#define LDSM_X4_T(r, addr)                                                     \
    asm volatile("ldmatrix.sync.aligned.m8n8.x4.trans.shared.b16 {%0,%1,%2,%3}, [%4];" \
        : "=r"((r)[0]), "=r"((r)[1]), "=r"((r)[2]), "=r"((r)[3]) : "r"(addr))

#define MMA_BF16(d, a, b)                                                      \
    asm volatile("mma.sync.aligned.m16n8k16.row.col.f32.bf16.bf16.f32 "        \
        "{%0,%1,%2,%3}, {%4,%5,%6,%7}, {%8,%9}, {%0,%1,%2,%3};"                \
        : "+f"((d)[0]), "+f"((d)[1]), "+f"((d)[2]), "+f"((d)[3])               \
        : "r"((a)[0]), "r"((a)[1]), "r"((a)[2]), "r"((a)[3]),                  \
          "r"((b)[0]), "r"((b)[1]))

__device__ __forceinline__ float gelu_f(float v) {
    const float c = 0.7978845608028654f;
    return 0.5f * v * (1.0f + tanhf(c * (v + 0.044715f * v * v * v)));
}
__device__ __forceinline__ void split_bf16(float v, __nv_bfloat16& hi, __nv_bfloat16& lo) {
    hi = __float2bfloat16(v);
    lo = __float2bfloat16(v - __bfloat162float(hi));
}
__device__ __forceinline__ void p2frag(float a, float b, uint32_t& hi, uint32_t& lo) {
    __nv_bfloat16 ha = __float2bfloat16(a), hb = __float2bfloat16(b);
    __nv_bfloat16 la = __float2bfloat16(a - __bfloat162float(ha));
    __nv_bfloat16 lb = __float2bfloat16(b - __bfloat162float(hb));
    __nv_bfloat162 H(ha, hb), L(la, lb);
    hi = *(uint32_t*)&H; lo = *(uint32_t*)&L;
}

// exp(x) for x <= 0, FMA/ALU pipes only (no MUFU, no CVT). rel err ~2.4e-6.
__device__ __forceinline__ float fexp(float x) {
    float t = fmaxf(x * 1.4426950408889634f, -126.0f);  // log2(e)*x, clamped
    float z = t + 12582912.0f;                          // 2^23 + 2^22: round
    int   e = __float_as_int(z);                        // low bits hold n
    float n = z - 12582912.0f;
    float f = t - n;                                    // f in [-0.5, 0.5]
    float p =             1.3333558146428443e-3f;
    p = fmaf(p, f,        9.6181291076284772e-3f);
    p = fmaf(p, f,        5.5504108664821580e-2f);
    p = fmaf(p, f,        2.4022650695910071e-1f);
    p = fmaf(p, f,        6.9314718055994531e-1f);
    p = fmaf(p, f,        1.0f);
    return __int_as_float(__float_as_int(p) + (e << 23));
}

// ---------------------------------------------------------------------------
// mma.sync GEMM: D[M,N] = (Ah+Al)[M,K] @ (Bh+Bl)[N,K]^T  (3 split terms)
// EP: 0=bias->f32  1/3=bias+res->f32  2=bias+gelu->bf16 hi/lo
//     4=bias, cols<C_DIM scaled by 0.125 -> bf16 hi/lo (qkv output)
// ---------------------------------------------------------------------------
template <int EP>
__global__ __launch_bounds__(256)
void mm_kernel(const __nv_bfloat16* __restrict__ Ah, const __nv_bfloat16* __restrict__ Al,
               const __nv_bfloat16* __restrict__ Bh, const __nv_bfloat16* __restrict__ Bl,
               const float* __restrict__ bias, const float* __restrict__ res,
               float* __restrict__ outF,
               __nv_bfloat16* __restrict__ outH, __nv_bfloat16* __restrict__ outL,
               int M, int N, int K)
{
    __shared__ __nv_bfloat16 Asm[2][128][40];
    __shared__ __nv_bfloat16 Bsm[2][128][40];

    int tid = threadIdx.x;
    int wid = tid >> 5, lane = tid & 31;
    int wm = wid & 3, wn = wid >> 2;
    int bm = blockIdx.y, bn = blockIdx.x;

    const int KC  = K / 32;
    const int NIT = 3 * KC;

    uint32_t sA[2] = { smem_u32(&Asm[0][0][0]), smem_u32(&Asm[1][0][0]) };
    uint32_t sB[2] = { smem_u32(&Bsm[0][0][0]), smem_u32(&Bsm[1][0][0]) };

    auto load_chunk = [&](int it2, int b2) {
        int term = it2 / KC;
        int k0 = (it2 - term * KC) * 32;
        const __nv_bfloat16* Ag = (term == 2) ? Al : Ah;
        const __nv_bfloat16* Bg = (term == 1) ? Bl : Bh;
        #pragma unroll
        for (int i = 0; i < 2; i++) {
            int s = tid + i * 256;
            int r = s >> 2, c = s & 3;
            CPA16(sA[b2] + r * 80 + c * 16,
                  (const char*)(Ag + (size_t)(bm * 128 + r) * K + k0) + c * 16);
            CPA16(sB[b2] + r * 80 + c * 16,
                  (const char*)(Bg + (size_t)(bn * 128 + r) * K + k0) + c * 16);
        }
    };

    float acc[2][8][4];
    #pragma unroll
    for (int i = 0; i < 2; i++)
        #pragma unroll
        for (int j = 0; j < 8; j++)
            #pragma unroll
            for (int q = 0; q < 4; q++) acc[i][j][q] = 0.f;

    load_chunk(0, 0); CP_COMMIT();
    load_chunk(1, 1); CP_COMMIT();

    int mrow = (lane & 7) + ((lane >> 3) & 1) * 8;
    int kgrp = (lane >> 4) * 8;

    for (int it = 0; it < NIT; ++it) {
        int b = it & 1;
        if (it + 1 < NIT) CP_WAIT1(); else CP_WAIT0();
        __syncthreads();

        #pragma unroll
        for (int ks = 0; ks < 2; ks++) {
            int kcol = ks * 16 + kgrp;
            uint32_t af[2][4], bf[4][4];
            #pragma unroll
            for (int mt = 0; mt < 2; mt++)
                LDSM_X4(af[mt], sA[b] + (wm * 32 + mt * 16 + mrow) * 80 + kcol * 2);
            #pragma unroll
            for (int np = 0; np < 4; np++)
                LDSM_X4(bf[np], sB[b] + (wn * 64 + np * 16 + mrow) * 80 + kcol * 2);
            #pragma unroll
            for (int mt = 0; mt < 2; mt++)
                #pragma unroll
                for (int nt = 0; nt < 8; nt++) {
                    uint32_t bb[2] = { bf[nt >> 1][nt & 1], bf[nt >> 1][(nt & 1) + 2] };
                    MMA_BF16(acc[mt][nt], af[mt], bb);
                }
        }
        __syncthreads();
        if (it + 2 < NIT) { load_chunk(it + 2, b); CP_COMMIT(); }
    }

    #pragma unroll
    for (int mt = 0; mt < 2; mt++) {
        int gr0 = bm * 128 + wm * 32 + mt * 16 + (lane >> 2);
        #pragma unroll
        for (int nt = 0; nt < 8; nt++) {
            int gc = bn * 128 + wn * 64 + nt * 8 + (lane & 3) * 2;
            float2 bi = *(const float2*)(bias + gc);
            #pragma unroll
            for (int h = 0; h < 2; h++) {
                int gr = gr0 + h * 8;
                float v0 = acc[mt][nt][h * 2 + 0] + bi.x;
                float v1 = acc[mt][nt][h * 2 + 1] + bi.y;
                size_t o = (size_t)gr * N + gc;
                if (EP == 1 || EP == 3) {
                    float2 rr = *(const float2*)(res + o);
                    v0 += rr.x; v1 += rr.y;
                }
                if (EP == 2 || EP == 4) {
                    if (EP == 2) { v0 = gelu_f(v0); v1 = gelu_f(v1); }
                    if (EP == 4 && gc < C_DIM) { v0 *= 0.125f; v1 *= 0.125f; }
                    __nv_bfloat16 h0, h1, l0, l1;
                    split_bf16(v0, h0, l0); split_bf16(v1, h1, l1);
                    *(__nv_bfloat162*)(outH + o) = __nv_bfloat162(h0, h1);
                    *(__nv_bfloat162*)(outL + o) = __nv_bfloat162(l0, l1);
                } else {
                    float2 ov = {v0, v1};
                    *(float2*)(outF + o) = ov;
                }
            }
        }
    }
}

// ---------------------------------------------------------------------------
// Transpose + hi/lo split:  w[K,N] f32 -> th/tl [N,K] bf16
// ---------------------------------------------------------------------------
__global__ __launch_bounds__(256) void tsplit_kernel(
    const float* __restrict__ w, __nv_bfloat16* __restrict__ th,
    __nv_bfloat16* __restrict__ tl, int K, int N)
{
    __shared__ float t[32][33];
    int n0 = blockIdx.x * 32, k0 = blockIdx.y * 32;
    int tx = threadIdx.x & 31, ty = threadIdx.x >> 5;
    #pragma unroll
    for (int j = 0; j < 4; j++) {
        int k = ty + j * 8;
        t[k][tx] = w[(size_t)(k0 + k) * N + n0 + tx];
    }
    __syncthreads();
    #pragma unroll
    for (int j = 0; j < 4; j++) {
        int nn = ty + j * 8;
        float v = t[tx][nn];
        __nv_bfloat16 hi, lo;
        split_bf16(v, hi, lo);
        size_t o = (size_t)(n0 + nn) * K + k0 + tx;
        th[o] = hi; tl[o] = lo;
    }
}

// ---------------------------------------------------------------------------
// LayerNorm -> bf16 hi/lo
// ---------------------------------------------------------------------------
__global__ __launch_bounds__(256) void ln_split_kernel(
    const float* __restrict__ x, const float* __restrict__ g,
    const float* __restrict__ b, __nv_bfloat16* __restrict__ oh,
    __nv_bfloat16* __restrict__ ol)
{
    int row = blockIdx.x;
    int tid = threadIdx.x;
    const float* xr = x + (size_t)row * C_DIM;

    float v0 = xr[tid], v1 = xr[tid + 256], v2 = xr[tid + 512];
    float s = v0 + v1 + v2;
    float sq = v0 * v0 + v1 * v1 + v2 * v2;
    #pragma unroll
    for (int o = 16; o > 0; o >>= 1) {
        s  += __shfl_xor_sync(0xffffffffu, s,  o);
        sq += __shfl_xor_sync(0xffffffffu, sq, o);
    }
    __shared__ float ss[8], sqs[8];
    int wid = tid >> 5, lane = tid & 31;
    if (lane == 0) { ss[wid] = s; sqs[wid] = sq; }
    __syncthreads();
    s = 0.f; sq = 0.f;
    #pragma unroll
    for (int i = 0; i < 8; i++) { s += ss[i]; sq += sqs[i]; }

    float mu = s * (1.0f / C_DIM);
    float var = sq * (1.0f / C_DIM) - mu * mu;
    float inv = rsqrtf(var + 1e-5f);

    size_t base = (size_t)row * C_DIM;
    #pragma unroll
    for (int e = 0; e < 3; e++) {
        int idx = tid + e * 256;
        float val = ((e == 0 ? v0 : e == 1 ? v1 : v2) - mu) * inv * g[idx] + b[idx];
        __nv_bfloat16 hi, lo;
        split_bf16(val, hi, lo);
        oh[base + idx] = hi; ol[base + idx] = lo;
    }
}

// ---------------------------------------------------------------------------
// Flash attention on mma.sync bf16, hi/lo split. qkv pre-split to bf16:
// pure cp.async tile loads (double-buffered K/V), Q frags register-hoisted,
// FMA-pipe exp. CTA: 128 queries x (head, batch); 8 warps x 16 rows.
// ---------------------------------------------------------------------------
#define ASTR 72
#define ATTN_SMEM2 (size_t)((2 * 128 * ASTR + 8 * 64 * ASTR) * sizeof(__nv_bfloat16))

__global__ __launch_bounds__(256) void attn_mma_kernel(
    const __nv_bfloat16* __restrict__ qh, const __nv_bfloat16* __restrict__ ql,
    __nv_bfloat16* __restrict__ yh, __nv_bfloat16* __restrict__ yl)
{
    extern __shared__ __nv_bfloat16 smb[];
    __nv_bfloat16* Qh = smb;
    __nv_bfloat16* Ql = Qh + 128 * ASTR;
    // KV buffers: [buf][arr: 0=Kh 1=Kl 2=Vh 3=Vl][64*ASTR]
    __nv_bfloat16* KV0 = Ql + 128 * ASTR;

    int qt = gridDim.x - 1 - blockIdx.x;   // heavy tiles first
    int hh = blockIdx.y, bb = blockIdx.z;
    int tid = threadIdx.x, wid = tid >> 5, lane = tid & 31;

    uint32_t sQh = smem_u32(Qh), sQl = smem_u32(Ql);
    uint32_t sKV[2][4];
    #pragma unroll
    for (int b2 = 0; b2 < 2; b2++)
        #pragma unroll
        for (int a2 = 0; a2 < 4; a2++)
            sKV[b2][a2] = smem_u32(KV0 + (b2 * 4 + a2) * 64 * ASTR);

    int mrow = (lane & 7) + ((lane >> 3) & 1) * 8;
    int kgrp = (lane >> 4) * 8;

    // ---- async load Q tile (pre-scaled, pre-split in gmem) ----
    {
        #pragma unroll
        for (int i = 0; i < 8; i++) {
            int s = tid + i * 256;          // 0..2047
            int arr = s >> 10;              // 0=h, 1=l
            int rem = s & 1023;
            int r = rem >> 3, c = rem & 7;
            const __nv_bfloat16* src = (arr ? ql : qh)
                + (size_t)(bb * T_SEQ + qt * 128 + r) * C3_DIM + hh * HD + c * 8;
            CPA16((arr ? sQl : sQh) + (r * ASTR + c * 8) * 2, src);
        }
    }

    auto load_kv = [&](int kt, int b2) {
        #pragma unroll
        for (int i = 0; i < 8; i++) {
            int s = tid + i * 256;          // 0..2047
            int arr = s >> 9;               // 0=Kh 1=Kl 2=Vh 3=Vl
            int rem = s & 511;
            int r = rem >> 3, c = rem & 7;
            int colb = ((arr < 2) ? C_DIM : 2 * C_DIM) + hh * HD;
            const __nv_bfloat16* src = ((arr & 1) ? ql : qh)
                + (size_t)(bb * T_SEQ + kt * 64 + r) * C3_DIM + colb + c * 8;
            CPA16(sKV[b2][arr] + (r * ASTR + c * 8) * 2, src);
        }
    };

    load_kv(0, 0); CP_COMMIT();   // group 0: Q + KV tile 0

    float m0 = -1e30f, m1 = -1e30f, l0 = 0.f, l1 = 0.f;
    float oacc[8][4];
    #pragma unroll
    for (int i = 0; i < 8; i++)
        #pragma unroll
        for (int j = 0; j < 4; j++) oacc[i][j] = 0.f;

    uint32_t qfh[4][4], qfl[4][4];

    int nkt = 2 * qt + 2;
    for (int kt = 0; kt < nkt; kt++) {
        int b = kt & 1;
        if (kt + 1 < nkt) { load_kv(kt + 1, b ^ 1); CP_COMMIT(); CP_WAIT1(); }
        else CP_WAIT0();
        __syncthreads();

        if (kt == 0) {
            #pragma unroll
            for (int kc = 0; kc < 4; kc++) {
                uint32_t aoff = ((wid * 16 + mrow) * ASTR + kc * 16 + kgrp) * 2;
                LDSM_X4(qfh[kc], sQh + aoff);
                LDSM_X4(qfl[kc], sQl + aoff);
            }
        }

        // ---- S = Q @ K^T  (3 hi/lo terms) ----
        float sacc[8][4];
        #pragma unroll
        for (int i = 0; i < 8; i++)
            #pragma unroll
            for (int j = 0; j < 4; j++) sacc[i][j] = 0.f;

        #pragma unroll
        for (int kc = 0; kc < 4; kc++) {
            #pragma unroll
            for (int ng = 0; ng < 4; ng++) {
                uint32_t bh[4], bl[4];
                uint32_t boff = ((ng * 16 + mrow) * ASTR + kc * 16 + kgrp) * 2;
                LDSM_X4(bh, sKV[b][0] + boff);
                LDSM_X4(bl, sKV[b][1] + boff);
                #pragma unroll
                for (int t = 0; t < 2; t++) {
                    uint32_t b0[2] = { bh[t], bh[t + 2] };
                    uint32_t b1[2] = { bl[t], bl[t + 2] };
                    MMA_BF16(sacc[ng * 2 + t], qfh[kc], b0);
                    MMA_BF16(sacc[ng * 2 + t], qfh[kc], b1);
                    MMA_BF16(sacc[ng * 2 + t], qfl[kc], b0);
                }
            }
        }

        // ---- causal mask ----
        int g0 = qt * 128 + wid * 16 + (lane >> 2);
        if (kt * 64 + 63 > qt * 128 + wid * 16) {
            #pragma unroll
            for (int nt = 0; nt < 8; nt++) {
                int kc0 = kt * 64 + nt * 8 + (lane & 3) * 2;
                if (kc0     > g0)     sacc[nt][0] = -1e30f;
                if (kc0 + 1 > g0)     sacc[nt][1] = -1e30f;
                if (kc0     > g0 + 8) sacc[nt][2] = -1e30f;
                if (kc0 + 1 > g0 + 8) sacc[nt][3] = -1e30f;
            }
        }

        // ---- online softmax (FMA-pipe exp) ----
        float mt0 = -1e30f, mt1 = -1e30f;
        #pragma unroll
        for (int nt = 0; nt < 8; nt++) {
            mt0 = fmaxf(mt0, fmaxf(sacc[nt][0], sacc[nt][1]));
            mt1 = fmaxf(mt1, fmaxf(sacc[nt][2], sacc[nt][3]));
        }
        mt0 = fmaxf(mt0, __shfl_xor_sync(0xffffffffu, mt0, 1));
        mt0 = fmaxf(mt0, __shfl_xor_sync(0xffffffffu, mt0, 2));
        mt1 = fmaxf(mt1, __shfl_xor_sync(0xffffffffu, mt1, 1));
        mt1 = fmaxf(mt1, __shfl_xor_sync(0xffffffffu, mt1, 2));

        float mn0 = fmaxf(m0, mt0), mn1 = fmaxf(m1, mt1);
        float c0 = fexp(m0 - mn0), c1 = fexp(m1 - mn1);
        m0 = mn0; m1 = mn1;

        float ps0 = 0.f, ps1 = 0.f;
        #pragma unroll
        for (int nt = 0; nt < 8; nt++) {
            sacc[nt][0] = fexp(sacc[nt][0] - m0);
            sacc[nt][1] = fexp(sacc[nt][1] - m0);
            sacc[nt][2] = fexp(sacc[nt][2] - m1);
            sacc[nt][3] = fexp(sacc[nt][3] - m1);
            ps0 += sacc[nt][0] + sacc[nt][1];
            ps1 += sacc[nt][2] + sacc[nt][3];
        }
        ps0 += __shfl_xor_sync(0xffffffffu, ps0, 1);
        ps0 += __shfl_xor_sync(0xffffffffu, ps0, 2);
        ps1 += __shfl_xor_sync(0xffffffffu, ps1, 1);
        ps1 += __shfl_xor_sync(0xffffffffu, ps1, 2);
        l0 = l0 * c0 + ps0;
        l1 = l1 * c1 + ps1;
        #pragma unroll
        for (int dt = 0; dt < 8; dt++) {
            oacc[dt][0] *= c0; oacc[dt][1] *= c0;
            oacc[dt][2] *= c1; oacc[dt][3] *= c1;
        }

        // ---- O += P @ V (3 hi/lo terms), P frags in-register ----
        #pragma unroll
        for (int kc = 0; kc < 4; kc++) {
            uint32_t ah[4], al[4];
            p2frag(sacc[2 * kc][0],     sacc[2 * kc][1],     ah[0], al[0]);
            p2frag(sacc[2 * kc][2],     sacc[2 * kc][3],     ah[1], al[1]);
            p2frag(sacc[2 * kc + 1][0], sacc[2 * kc + 1][1], ah[2], al[2]);
            p2frag(sacc[2 * kc + 1][2], sacc[2 * kc + 1][3], ah[3], al[3]);
            #pragma unroll
            for (int ng = 0; ng < 4; ng++) {
                uint32_t bvh[4], bvl[4];
                uint32_t voff = ((kc * 16 + ((lane >> 3) & 1) * 8 + (lane & 7)) * ASTR
                                 + ng * 16 + (lane >> 4) * 8) * 2;
                LDSM_X4_T(bvh, sKV[b][2] + voff);
                LDSM_X4_T(bvl, sKV[b][3] + voff);
                #pragma unroll
                for (int t = 0; t < 2; t++) {
                    int dt = ng * 2 + t;
                    uint32_t b0[2] = { bvh[2 * t], bvh[2 * t + 1] };
                    uint32_t b1[2] = { bvl[2 * t], bvl[2 * t + 1] };
                    MMA_BF16(oacc[dt], ah, b0);
                    MMA_BF16(oacc[dt], ah, b1);
                    MMA_BF16(oacc[dt], al, b0);
                }
            }
        }
        __syncthreads();   // done with buffer b before it is refilled
    }

    // ---- epilogue: normalize, split hi/lo, store ----
    float i0 = 1.0f / l0, i1 = 1.0f / l1;
    int gr0 = qt * 128 + wid * 16 + (lane >> 2);
    #pragma unroll
    for (int dt = 0; dt < 8; dt++) {
        int col = hh * HD + dt * 8 + (lane & 3) * 2;
        size_t o0 = ((size_t)(bb * T_SEQ + gr0)) * C_DIM + col;
        size_t o1 = ((size_t)(bb * T_SEQ + gr0 + 8)) * C_DIM + col;
        __nv_bfloat16 ha, la, hb, lb;
        split_bf16(oacc[dt][0] * i0, ha, la);
        split_bf16(oacc[dt][1] * i0, hb, lb);
        *(__nv_bfloat162*)(yh + o0) = __nv_bfloat162(ha, hb);
        *(__nv_bfloat162*)(yl + o0) = __nv_bfloat162(la, lb);
        split_bf16(oacc[dt][2] * i1, ha, la);
        split_bf16(oacc[dt][3] * i1, hb, lb);
        *(__nv_bfloat162*)(yh + o1) = __nv_bfloat162(ha, hb);
        *(__nv_bfloat162*)(yl + o1) = __nv_bfloat162(la, lb);
    }
}

// ---------------------------------------------------------------------------
// Launch
// ---------------------------------------------------------------------------
extern "C" void kernel_launch(void* const* d_in, const int* in_sizes, int n_in,
                              void* d_out, int out_size)
{
    const float* x           = (const float*)d_in[0];
    const float* ln1_g       = (const float*)d_in[1];
    const float* ln1_b       = (const float*)d_in[2];
    const float* w_attn      = (const float*)d_in[3];
    const float* b_attn      = (const float*)d_in[4];
    const float* w_attn_proj = (const float*)d_in[5];
    const float* b_attn_proj = (const float*)d_in[6];
    const float* ln2_g       = (const float*)d_in[7];
    const float* ln2_b       = (const float*)d_in[8];
    const float* w_fc        = (const float*)d_in[9];
    const float* b_fc        = (const float*)d_in[10];
    const float* w_mlp_proj  = (const float*)d_in[11];
    const float* b_mlp_proj  = (const float*)d_in[12];
    float* out = (float*)d_out;

    float *x1;
    __nv_bfloat16 *qkvh, *qkvl;
    __nv_bfloat16 *hh, *hl, *yh, *yl, *h2h, *h2l, *uh, *ul;
    __nv_bfloat16 *wqh, *wql, *wph, *wpl, *wfh, *wfl, *wmh, *wml;
    cudaGetSymbolAddress((void**)&x1,   g_x1);
    cudaGetSymbolAddress((void**)&qkvh, g_qkvh); cudaGetSymbolAddress((void**)&qkvl, g_qkvl);
    cudaGetSymbolAddress((void**)&hh,  g_hh);  cudaGetSymbolAddress((void**)&hl,  g_hl);
    cudaGetSymbolAddress((void**)&yh,  g_yh);  cudaGetSymbolAddress((void**)&yl,  g_yl);
    cudaGetSymbolAddress((void**)&h2h, g_h2h); cudaGetSymbolAddress((void**)&h2l, g_h2l);
    cudaGetSymbolAddress((void**)&uh,  g_uh);  cudaGetSymbolAddress((void**)&ul,  g_ul);
    cudaGetSymbolAddress((void**)&wqh, g_wqh); cudaGetSymbolAddress((void**)&wql, g_wql);
    cudaGetSymbolAddress((void**)&wph, g_wph); cudaGetSymbolAddress((void**)&wpl, g_wpl);
    cudaGetSymbolAddress((void**)&wfh, g_wfh); cudaGetSymbolAddress((void**)&wfl, g_wfl);
    cudaGetSymbolAddress((void**)&wmh, g_wmh); cudaGetSymbolAddress((void**)&wml, g_wml);

    cudaFuncSetAttribute(attn_mma_kernel,
        cudaFuncAttributeMaxDynamicSharedMemorySize, (int)ATTN_SMEM2);

    // weight transpose + split
    tsplit_kernel<<<dim3(C3_DIM / 32, C_DIM / 32), 256>>>(w_attn, wqh, wql, C_DIM, C3_DIM);
    tsplit_kernel<<<dim3(C_DIM / 32, C_DIM / 32), 256>>>(w_attn_proj, wph, wpl, C_DIM, C_DIM);
    tsplit_kernel<<<dim3(C4_DIM / 32, C_DIM / 32), 256>>>(w_fc, wfh, wfl, C_DIM, C4_DIM);
    tsplit_kernel<<<dim3(C_DIM / 32, C4_DIM / 32), 256>>>(w_mlp_proj, wmh, wml, C4_DIM, C_DIM);

    // 1. LN1 -> bf16 hi/lo
    ln_split_kernel<<<M_ROWS, 256>>>(x, ln1_g, ln1_b, hh, hl);
    // 2. qkv = h @ w_attn + b  -> bf16 hi/lo, Q cols pre-scaled by 1/8
    mm_kernel<4><<<dim3(C3_DIM / 128, M_ROWS / 128), 256>>>(
        hh, hl, wqh, wql, b_attn, nullptr, nullptr, qkvh, qkvl,
        M_ROWS, C3_DIM, C_DIM);
    // 3. attention (tensor-core flash) -> y hi/lo
    attn_mma_kernel<<<dim3(T_SEQ / 128, N_HEAD, 2), 256, ATTN_SMEM2>>>(
        qkvh, qkvl, yh, yl);
    // 4. x1 = x + y @ w_attn_proj + b
    mm_kernel<1><<<dim3(C_DIM / 128, M_ROWS / 128), 256>>>(
        yh, yl, wph, wpl, b_attn_proj, x, x1, nullptr, nullptr,
        M_ROWS, C_DIM, C_DIM);
    // 5. LN2 -> bf16 hi/lo
    ln_split_kernel<<<M_ROWS, 256>>>(x1, ln2_g, ln2_b, h2h, h2l);
    // 6. u = gelu(h2 @ w_fc + b) -> bf16 hi/lo
    mm_kernel<2><<<dim3(C4_DIM / 128, M_ROWS / 128), 256>>>(
        h2h, h2l, wfh, wfl, b_fc, nullptr, nullptr, uh, ul,
        M_ROWS, C4_DIM, C_DIM);
    // 7. out = x1 + u @ w_mlp_proj + b
    mm_kernel<3><<<dim3(C_DIM / 128, M_ROWS / 128), 256>>>(
        uh, ul, wmh, wml, b_mlp_proj, x1, out, nullptr, nullptr,
        M_ROWS, C_DIM, C4_DIM);
}

// round 12
// speedup vs baseline: 1.0114x; 1.0114x over previous
#include <cuda_runtime.h>
#include <cuda_bf16.h>
#include <math.h>
#include <stdint.h>

// ---------------------------------------------------------------------------
// GPT-2 transformer block. GEMMs + attention on mma.sync bf16 (hi/lo split).
// Attention: pre-split bf16 qkv, Q folded into KV smem (72KB, 2 CTA/SM),
// double-buffered cp.async K/V, FMA-pipe exp.
// B=2, T=2048, C=768, H=12, hd=64.  M = B*T = 4096.
// ---------------------------------------------------------------------------

#define M_ROWS 4096
#define C_DIM  768
#define C3_DIM 2304
#define C4_DIM 3072
#define N_HEAD 12
#define HD     64
#define T_SEQ  2048

// ---------------- scratch (device globals) ----------------
__device__ float g_x1 [M_ROWS * C_DIM];
__device__ __nv_bfloat16 g_qkvh[M_ROWS * C3_DIM], g_qkvl[M_ROWS * C3_DIM];
__device__ __nv_bfloat16 g_hh [M_ROWS * C_DIM],  g_hl [M_ROWS * C_DIM];
__device__ __nv_bfloat16 g_yh [M_ROWS * C_DIM],  g_yl [M_ROWS * C_DIM];
__device__ __nv_bfloat16 g_h2h[M_ROWS * C_DIM],  g_h2l[M_ROWS * C_DIM];
__device__ __nv_bfloat16 g_uh [M_ROWS * C4_DIM], g_ul [M_ROWS * C4_DIM];
__device__ __nv_bfloat16 g_wqh[C3_DIM * C_DIM],  g_wql[C3_DIM * C_DIM];
__device__ __nv_bfloat16 g_wph[C_DIM * C_DIM],   g_wpl[C_DIM * C_DIM];
__device__ __nv_bfloat16 g_wfh[C4_DIM * C_DIM],  g_wfl[C4_DIM * C_DIM];
__device__ __nv_bfloat16 g_wmh[C_DIM * C4_DIM],  g_wml[C_DIM * C4_DIM];

// ---------------- PTX helpers (base ISA only) ----------
__device__ __forceinline__ uint32_t smem_u32(const void* p) {
    uint32_t a;
    asm("{ .reg .u64 t; cvta.to.shared.u64 t, %1; cvt.u32.u64 %0, t; }"
        : "=r"(a) : "l"(p));
    return a;
}

#define CPA16(dst, src) \
    asm volatile("cp.async.cg.shared.global [%0], [%1], 16;" :: "r"(dst), "l"(src))
#define CP_COMMIT() asm volatile("cp.async.commit_group;" ::: "memory")
#define CP_WAIT1()  asm volatile("cp.async.wait_group 1;" ::: "memory")
#define CP_WAIT0()  asm volatile("cp.async.wait_group 0;" ::: "memory")

#define LDSM_X4(r, addr)                                                       \
    asm volatile("ldmatrix.sync.aligned.m8n8.x4.shared.b16 {%0,%1,%2,%3}, [%4];" \
        : "=r"((r)[0]), "=r"((r)[1]), "=r"((r)[2]), "=r"((r)[3]) : "r"(addr))

#define LDSM_X4_T(r, addr)                                                     \
    asm volatile("ldmatrix.sync.aligned.m8n8.x4.trans.shared.b16 {%0,%1,%2,%3}, [%4];" \
        : "=r"((r)[0]), "=r"((r)[1]), "=r"((r)[2]), "=r"((r)[3]) : "r"(addr))

#define MMA_BF16(d, a, b)                                                      \
    asm volatile("mma.sync.aligned.m16n8k16.row.col.f32.bf16.bf16.f32 "        \
        "{%0,%1,%2,%3}, {%4,%5,%6,%7}, {%8,%9}, {%0,%1,%2,%3};"                \
        : "+f"((d)[0]), "+f"((d)[1]), "+f"((d)[2]), "+f"((d)[3])               \
        : "r"((a)[0]), "r"((a)[1]), "r"((a)[2]), "r"((a)[3]),                  \
          "r"((b)[0]), "r"((b)[1]))

__device__ __forceinline__ float gelu_f(float v) {
    const float c = 0.7978845608028654f;
    return 0.5f * v * (1.0f + tanhf(c * (v + 0.044715f * v * v * v)));
}
__device__ __forceinline__ void split_bf16(float v, __nv_bfloat16& hi, __nv_bfloat16& lo) {
    hi = __float2bfloat16(v);
    lo = __float2bfloat16(v - __bfloat162float(hi));
}
__device__ __forceinline__ void p2frag(float a, float b, uint32_t& hi, uint32_t& lo) {
    __nv_bfloat16 ha = __float2bfloat16(a), hb = __float2bfloat16(b);
    __nv_bfloat16 la = __float2bfloat16(a - __bfloat162float(ha));
    __nv_bfloat16 lb = __float2bfloat16(b - __bfloat162float(hb));
    __nv_bfloat162 H(ha, hb), L(la, lb);
    hi = *(uint32_t*)&H; lo = *(uint32_t*)&L;
}

// exp(x) for x <= 0, FMA/ALU pipes only. rel err ~2.4e-6.
__device__ __forceinline__ float fexp(float x) {
    float t = fmaxf(x * 1.4426950408889634f, -126.0f);
    float z = t + 12582912.0f;
    int   e = __float_as_int(z);
    float n = z - 12582912.0f;
    float f = t - n;
    float p =             1.3333558146428443e-3f;
    p = fmaf(p, f,        9.6181291076284772e-3f);
    p = fmaf(p, f,        5.5504108664821580e-2f);
    p = fmaf(p, f,        2.4022650695910071e-1f);
    p = fmaf(p, f,        6.9314718055994531e-1f);
    p = fmaf(p, f,        1.0f);
    return __int_as_float(__float_as_int(p) + (e << 23));
}

// ---------------------------------------------------------------------------
// mma.sync GEMM: D[M,N] = (Ah+Al)[M,K] @ (Bh+Bl)[N,K]^T  (3 split terms)
// EP: 0=bias->f32  1/3=bias+res->f32  2=bias+gelu->bf16 hi/lo
//     4=bias, cols<C_DIM scaled by 0.125 -> bf16 hi/lo (qkv output)
// ---------------------------------------------------------------------------
template <int EP>
__global__ __launch_bounds__(256)
void mm_kernel(const __nv_bfloat16* __restrict__ Ah, const __nv_bfloat16* __restrict__ Al,
               const __nv_bfloat16* __restrict__ Bh, const __nv_bfloat16* __restrict__ Bl,
               const float* __restrict__ bias, const float* __restrict__ res,
               float* __restrict__ outF,
               __nv_bfloat16* __restrict__ outH, __nv_bfloat16* __restrict__ outL,
               int M, int N, int K)
{
    __shared__ __nv_bfloat16 Asm[2][128][40];
    __shared__ __nv_bfloat16 Bsm[2][128][40];

    int tid = threadIdx.x;
    int wid = tid >> 5, lane = tid & 31;
    int wm = wid & 3, wn = wid >> 2;
    int bm = blockIdx.y, bn = blockIdx.x;

    const int KC  = K / 32;
    const int NIT = 3 * KC;

    uint32_t sA[2] = { smem_u32(&Asm[0][0][0]), smem_u32(&Asm[1][0][0]) };
    uint32_t sB[2] = { smem_u32(&Bsm[0][0][0]), smem_u32(&Bsm[1][0][0]) };

    auto load_chunk = [&](int it2, int b2) {
        int term = it2 / KC;
        int k0 = (it2 - term * KC) * 32;
        const __nv_bfloat16* Ag = (term == 2) ? Al : Ah;
        const __nv_bfloat16* Bg = (term == 1) ? Bl : Bh;
        #pragma unroll
        for (int i = 0; i < 2; i++) {
            int s = tid + i * 256;
            int r = s >> 2, c = s & 3;
            CPA16(sA[b2] + r * 80 + c * 16,
                  (const char*)(Ag + (size_t)(bm * 128 + r) * K + k0) + c * 16);
            CPA16(sB[b2] + r * 80 + c * 16,
                  (const char*)(Bg + (size_t)(bn * 128 + r) * K + k0) + c * 16);
        }
    };

    float acc[2][8][4];
    #pragma unroll
    for (int i = 0; i < 2; i++)
        #pragma unroll
        for (int j = 0; j < 8; j++)
            #pragma unroll
            for (int q = 0; q < 4; q++) acc[i][j][q] = 0.f;

    load_chunk(0, 0); CP_COMMIT();
    load_chunk(1, 1); CP_COMMIT();

    int mrow = (lane & 7) + ((lane >> 3) & 1) * 8;
    int kgrp = (lane >> 4) * 8;

    for (int it = 0; it < NIT; ++it) {
        int b = it & 1;
        if (it + 1 < NIT) CP_WAIT1(); else CP_WAIT0();
        __syncthreads();

        #pragma unroll
        for (int ks = 0; ks < 2; ks++) {
            int kcol = ks * 16 + kgrp;
            uint32_t af[2][4], bf[4][4];
            #pragma unroll
            for (int mt = 0; mt < 2; mt++)
                LDSM_X4(af[mt], sA[b] + (wm * 32 + mt * 16 + mrow) * 80 + kcol * 2);
            #pragma unroll
            for (int np = 0; np < 4; np++)
                LDSM_X4(bf[np], sB[b] + (wn * 64 + np * 16 + mrow) * 80 + kcol * 2);
            #pragma unroll
            for (int mt = 0; mt < 2; mt++)
                #pragma unroll
                for (int nt = 0; nt < 8; nt++) {
                    uint32_t bb[2] = { bf[nt >> 1][nt & 1], bf[nt >> 1][(nt & 1) + 2] };
                    MMA_BF16(acc[mt][nt], af[mt], bb);
                }
        }
        __syncthreads();
        if (it + 2 < NIT) { load_chunk(it + 2, b); CP_COMMIT(); }
    }

    #pragma unroll
    for (int mt = 0; mt < 2; mt++) {
        int gr0 = bm * 128 + wm * 32 + mt * 16 + (lane >> 2);
        #pragma unroll
        for (int nt = 0; nt < 8; nt++) {
            int gc = bn * 128 + wn * 64 + nt * 8 + (lane & 3) * 2;
            float2 bi = *(const float2*)(bias + gc);
            #pragma unroll
            for (int h = 0; h < 2; h++) {
                int gr = gr0 + h * 8;
                float v0 = acc[mt][nt][h * 2 + 0] + bi.x;
                float v1 = acc[mt][nt][h * 2 + 1] + bi.y;
                size_t o = (size_t)gr * N + gc;
                if (EP == 1 || EP == 3) {
                    float2 rr = *(const float2*)(res + o);
                    v0 += rr.x; v1 += rr.y;
                }
                if (EP == 2 || EP == 4) {
                    if (EP == 2) { v0 = gelu_f(v0); v1 = gelu_f(v1); }
                    if (EP == 4 && gc < C_DIM) { v0 *= 0.125f; v1 *= 0.125f; }
                    __nv_bfloat16 h0, h1, l0, l1;
                    split_bf16(v0, h0, l0); split_bf16(v1, h1, l1);
                    *(__nv_bfloat162*)(outH + o) = __nv_bfloat162(h0, h1);
                    *(__nv_bfloat162*)(outL + o) = __nv_bfloat162(l0, l1);
                } else {
                    float2 ov = {v0, v1};
                    *(float2*)(outF + o) = ov;
                }
            }
        }
    }
}

// ---------------------------------------------------------------------------
// Transpose + hi/lo split:  w[K,N] f32 -> th/tl [N,K] bf16
// ---------------------------------------------------------------------------
__global__ __launch_bounds__(256) void tsplit_kernel(
    const float* __restrict__ w, __nv_bfloat16* __restrict__ th,
    __nv_bfloat16* __restrict__ tl, int K, int N)
{
    __shared__ float t[32][33];
    int n0 = blockIdx.x * 32, k0 = blockIdx.y * 32;
    int tx = threadIdx.x & 31, ty = threadIdx.x >> 5;
    #pragma unroll
    for (int j = 0; j < 4; j++) {
        int k = ty + j * 8;
        t[k][tx] = w[(size_t)(k0 + k) * N + n0 + tx];
    }
    __syncthreads();
    #pragma unroll
    for (int j = 0; j < 4; j++) {
        int nn = ty + j * 8;
        float v = t[tx][nn];
        __nv_bfloat16 hi, lo;
        split_bf16(v, hi, lo);
        size_t o = (size_t)(n0 + nn) * K + k0 + tx;
        th[o] = hi; tl[o] = lo;
    }
}

// ---------------------------------------------------------------------------
// LayerNorm -> bf16 hi/lo
// ---------------------------------------------------------------------------
__global__ __launch_bounds__(256) void ln_split_kernel(
    const float* __restrict__ x, const float* __restrict__ g,
    const float* __restrict__ b, __nv_bfloat16* __restrict__ oh,
    __nv_bfloat16* __restrict__ ol)
{
    int row = blockIdx.x;
    int tid = threadIdx.x;
    const float* xr = x + (size_t)row * C_DIM;

    float v0 = xr[tid], v1 = xr[tid + 256], v2 = xr[tid + 512];
    float s = v0 + v1 + v2;
    float sq = v0 * v0 + v1 * v1 + v2 * v2;
    #pragma unroll
    for (int o = 16; o > 0; o >>= 1) {
        s  += __shfl_xor_sync(0xffffffffu, s,  o);
        sq += __shfl_xor_sync(0xffffffffu, sq, o);
    }
    __shared__ float ss[8], sqs[8];
    int wid = tid >> 5, lane = tid & 31;
    if (lane == 0) { ss[wid] = s; sqs[wid] = sq; }
    __syncthreads();
    s = 0.f; sq = 0.f;
    #pragma unroll
    for (int i = 0; i < 8; i++) { s += ss[i]; sq += sqs[i]; }

    float mu = s * (1.0f / C_DIM);
    float var = sq * (1.0f / C_DIM) - mu * mu;
    float inv = rsqrtf(var + 1e-5f);

    size_t base = (size_t)row * C_DIM;
    #pragma unroll
    for (int e = 0; e < 3; e++) {
        int idx = tid + e * 256;
        float val = ((e == 0 ? v0 : e == 1 ? v1 : v2) - mu) * inv * g[idx] + b[idx];
        __nv_bfloat16 hi, lo;
        split_bf16(val, hi, lo);
        oh[base + idx] = hi; ol[base + idx] = lo;
    }
}

// ---------------------------------------------------------------------------
// Flash attention on mma.sync bf16, hi/lo split. Q folded into the KV double
// buffer (Q frags hoisted to registers before KV loads overwrite it).
// smem = 2 bufs x 4 arrays x 64 x ASTR bf16 = 72KB -> 2 CTAs/SM (regs capped).
// CTA: 128 queries x (head, batch); 8 warps x 16 rows.
// ---------------------------------------------------------------------------
#define ASTR 72
#define KVBUF (64 * ASTR)
#define ATTN_SMEM2 (size_t)(8 * KVBUF * sizeof(__nv_bfloat16))

__global__ __launch_bounds__(256, 2) void attn_mma_kernel(
    const __nv_bfloat16* __restrict__ qh, const __nv_bfloat16* __restrict__ ql,
    __nv_bfloat16* __restrict__ yh, __nv_bfloat16* __restrict__ yl)
{
    extern __shared__ __nv_bfloat16 smb[];
    uint32_t sbase = smem_u32(smb);

    // KV buffers: [buf][arr: 0=Kh 1=Kl 2=Vh 3=Vl]
    uint32_t sKV[2][4];
    #pragma unroll
    for (int b2 = 0; b2 < 2; b2++)
        #pragma unroll
        for (int a2 = 0; a2 < 4; a2++)
            sKV[b2][a2] = sbase + (b2 * 4 + a2) * KVBUF * 2;
    // Q staging aliases buf0: Qh in arrays 0-1, Ql in arrays 2-3 (128 rows each)
    uint32_t sQh = sbase;
    uint32_t sQl = sbase + 2 * KVBUF * 2;

    int qt = gridDim.x - 1 - blockIdx.x;   // heavy tiles first
    int hh = blockIdx.y, bb = blockIdx.z;
    int tid = threadIdx.x, wid = tid >> 5, lane = tid & 31;

    int mrow = (lane & 7) + ((lane >> 3) & 1) * 8;
    int kgrp = (lane >> 4) * 8;

    auto load_kv = [&](int kt, int b2) {
        #pragma unroll
        for (int i = 0; i < 8; i++) {
            int s = tid + i * 256;          // 0..2047
            int arr = s >> 9;               // 0=Kh 1=Kl 2=Vh 3=Vl
            int rem = s & 511;
            int r = rem >> 3, c = rem & 7;
            int colb = ((arr < 2) ? C_DIM : 2 * C_DIM) + hh * HD;
            const __nv_bfloat16* src = ((arr & 1) ? ql : qh)
                + (size_t)(bb * T_SEQ + kt * 64 + r) * C3_DIM + colb + c * 8;
            CPA16(sKV[b2][arr] + (r * ASTR + c * 8) * 2, src);
        }
    };

    // ---- group 0: Q into buf0 region ----
    #pragma unroll
    for (int i = 0; i < 8; i++) {
        int s = tid + i * 256;              // 0..2047
        int arr = s >> 10;                  // 0=h, 1=l
        int rem = s & 1023;
        int r = rem >> 3, c = rem & 7;
        const __nv_bfloat16* src = (arr ? ql : qh)
            + (size_t)(bb * T_SEQ + qt * 128 + r) * C3_DIM + hh * HD + c * 8;
        CPA16((arr ? sQl : sQh) + (r * ASTR + c * 8) * 2, src);
    }
    CP_COMMIT();
    // ---- group 1: KV tile 0 into buf1 ----
    load_kv(0, 1); CP_COMMIT();

    CP_WAIT1();          // Q complete (KV0 may still be in flight)
    __syncthreads();

    // hoist Q fragments to registers, then release buf0 for KV reuse
    uint32_t qfh[4][4], qfl[4][4];
    #pragma unroll
    for (int kc = 0; kc < 4; kc++) {
        uint32_t aoff = ((wid * 16 + mrow) * ASTR + kc * 16 + kgrp) * 2;
        LDSM_X4(qfh[kc], sQh + aoff);
        LDSM_X4(qfl[kc], sQl + aoff);
    }
    __syncthreads();     // all warps done reading Q smem

    float m0 = -1e30f, m1 = -1e30f, l0 = 0.f, l1 = 0.f;
    float oacc[8][4];
    #pragma unroll
    for (int i = 0; i < 8; i++)
        #pragma unroll
        for (int j = 0; j < 4; j++) oacc[i][j] = 0.f;

    int nkt = 2 * qt + 2;
    for (int kt = 0; kt < nkt; kt++) {
        int b = (kt + 1) & 1;               // buffer holding KV_kt
        if (kt + 1 < nkt) { load_kv(kt + 1, b ^ 1); CP_COMMIT(); CP_WAIT1(); }
        else CP_WAIT0();
        __syncthreads();

        // ---- S = Q @ K^T  (3 hi/lo terms) ----
        float sacc[8][4];
        #pragma unroll
        for (int i = 0; i < 8; i++)
            #pragma unroll
            for (int j = 0; j < 4; j++) sacc[i][j] = 0.f;

        #pragma unroll
        for (int kc = 0; kc < 4; kc++) {
            #pragma unroll
            for (int ng = 0; ng < 4; ng++) {
                uint32_t bh[4], bl[4];
                uint32_t boff = ((ng * 16 + mrow) * ASTR + kc * 16 + kgrp) * 2;
                LDSM_X4(bh, sKV[b][0] + boff);
                LDSM_X4(bl, sKV[b][1] + boff);
                #pragma unroll
                for (int t = 0; t < 2; t++) {
                    uint32_t b0[2] = { bh[t], bh[t + 2] };
                    uint32_t b1[2] = { bl[t], bl[t + 2] };
                    MMA_BF16(sacc[ng * 2 + t], qfh[kc], b0);
                    MMA_BF16(sacc[ng * 2 + t], qfh[kc], b1);
                    MMA_BF16(sacc[ng * 2 + t], qfl[kc], b0);
                }
            }
        }

        // ---- causal mask ----
        int g0 = qt * 128 + wid * 16 + (lane >> 2);
        if (kt * 64 + 63 > qt * 128 + wid * 16) {
            #pragma unroll
            for (int nt = 0; nt < 8; nt++) {
                int kc0 = kt * 64 + nt * 8 + (lane & 3) * 2;
                if (kc0     > g0)     sacc[nt][0] = -1e30f;
                if (kc0 + 1 > g0)     sacc[nt][1] = -1e30f;
                if (kc0     > g0 + 8) sacc[nt][2] = -1e30f;
                if (kc0 + 1 > g0 + 8) sacc[nt][3] = -1e30f;
            }
        }

        // ---- online softmax (FMA-pipe exp) ----
        float mt0 = -1e30f, mt1 = -1e30f;
        #pragma unroll
        for (int nt = 0; nt < 8; nt++) {
            mt0 = fmaxf(mt0, fmaxf(sacc[nt][0], sacc[nt][1]));
            mt1 = fmaxf(mt1, fmaxf(sacc[nt][2], sacc[nt][3]));
        }
        mt0 = fmaxf(mt0, __shfl_xor_sync(0xffffffffu, mt0, 1));
        mt0 = fmaxf(mt0, __shfl_xor_sync(0xffffffffu, mt0, 2));
        mt1 = fmaxf(mt1, __shfl_xor_sync(0xffffffffu, mt1, 1));
        mt1 = fmaxf(mt1, __shfl_xor_sync(0xffffffffu, mt1, 2));

        float mn0 = fmaxf(m0, mt0), mn1 = fmaxf(m1, mt1);
        float c0 = fexp(m0 - mn0), c1 = fexp(m1 - mn1);
        m0 = mn0; m1 = mn1;

        float ps0 = 0.f, ps1 = 0.f;
        #pragma unroll
        for (int nt = 0; nt < 8; nt++) {
            sacc[nt][0] = fexp(sacc[nt][0] - m0);
            sacc[nt][1] = fexp(sacc[nt][1] - m0);
            sacc[nt][2] = fexp(sacc[nt][2] - m1);
            sacc[nt][3] = fexp(sacc[nt][3] - m1);
            ps0 += sacc[nt][0] + sacc[nt][1];
            ps1 += sacc[nt][2] + sacc[nt][3];
        }
        ps0 += __shfl_xor_sync(0xffffffffu, ps0, 1);
        ps0 += __shfl_xor_sync(0xffffffffu, ps0, 2);
        ps1 += __shfl_xor_sync(0xffffffffu, ps1, 1);
        ps1 += __shfl_xor_sync(0xffffffffu, ps1, 2);
        l0 = l0 * c0 + ps0;
        l1 = l1 * c1 + ps1;
        #pragma unroll
        for (int dt = 0; dt < 8; dt++) {
            oacc[dt][0] *= c0; oacc[dt][1] *= c0;
            oacc[dt][2] *= c1; oacc[dt][3] *= c1;
        }

        // ---- O += P @ V (3 hi/lo terms), P frags in-register ----
        #pragma unroll
        for (int kc = 0; kc < 4; kc++) {
            uint32_t ah[4], al[4];
            p2frag(sacc[2 * kc][0],     sacc[2 * kc][1],     ah[0], al[0]);
            p2frag(sacc[2 * kc][2],     sacc[2 * kc][3],     ah[1], al[1]);
            p2frag(sacc[2 * kc + 1][0], sacc[2 * kc + 1][1], ah[2], al[2]);
            p2frag(sacc[2 * kc + 1][2], sacc[2 * kc + 1][3], ah[3], al[3]);
            #pragma unroll
            for (int ng = 0; ng < 4; ng++) {
                uint32_t bvh[4], bvl[4];
                uint32_t voff = ((kc * 16 + ((lane >> 3) & 1) * 8 + (lane & 7)) * ASTR
                                 + ng * 16 + (lane >> 4) * 8) * 2;
                LDSM_X4_T(bvh, sKV[b][2] + voff);
                LDSM_X4_T(bvl, sKV[b][3] + voff);
                #pragma unroll
                for (int t = 0; t < 2; t++) {
                    int dt = ng * 2 + t;
                    uint32_t b0[2] = { bvh[2 * t], bvh[2 * t + 1] };
                    uint32_t b1[2] = { bvl[2 * t], bvl[2 * t + 1] };
                    MMA_BF16(oacc[dt], ah, b0);
                    MMA_BF16(oacc[dt], ah, b1);
                    MMA_BF16(oacc[dt], al, b0);
                }
            }
        }
        __syncthreads();   // all warps done with buffer b before refill
    }

    // ---- epilogue: normalize, split hi/lo, store ----
    float i0 = 1.0f / l0, i1 = 1.0f / l1;
    int gr0 = qt * 128 + wid * 16 + (lane >> 2);
    #pragma unroll
    for (int dt = 0; dt < 8; dt++) {
        int col = hh * HD + dt * 8 + (lane & 3) * 2;
        size_t o0 = ((size_t)(bb * T_SEQ + gr0)) * C_DIM + col;
        size_t o1 = ((size_t)(bb * T_SEQ + gr0 + 8)) * C_DIM + col;
        __nv_bfloat16 ha, la, hb, lb;
        split_bf16(oacc[dt][0] * i0, ha, la);
        split_bf16(oacc[dt][1] * i0, hb, lb);
        *(__nv_bfloat162*)(yh + o0) = __nv_bfloat162(ha, hb);
        *(__nv_bfloat162*)(yl + o0) = __nv_bfloat162(la, lb);
        split_bf16(oacc[dt][2] * i1, ha, la);
        split_bf16(oacc[dt][3] * i1, hb, lb);
        *(__nv_bfloat162*)(yh + o1) = __nv_bfloat162(ha, hb);
        *(__nv_bfloat162*)(yl + o1) = __nv_bfloat162(la, lb);
    }
}

// ---------------------------------------------------------------------------
// Launch
// ---------------------------------------------------------------------------
extern "C" void kernel_launch(void* const* d_in, const int* in_sizes, int n_in,
                              void* d_out, int out_size)
{
    const float* x           = (const float*)d_in[0];
    const float* ln1_g       = (const float*)d_in[1];
    const float* ln1_b       = (const float*)d_in[2];
    const float* w_attn      = (const float*)d_in[3];
    const float* b_attn      = (const float*)d_in[4];
    const float* w_attn_proj = (const float*)d_in[5];
    const float* b_attn_proj = (const float*)d_in[6];
    const float* ln2_g       = (const float*)d_in[7];
    const float* ln2_b       = (const float*)d_in[8];
    const float* w_fc        = (const float*)d_in[9];
    const float* b_fc        = (const float*)d_in[10];
    const float* w_mlp_proj  = (const float*)d_in[11];
    const float* b_mlp_proj  = (const float*)d_in[12];
    float* out = (float*)d_out;

    float *x1;
    __nv_bfloat16 *qkvh, *qkvl;
    __nv_bfloat16 *hh, *hl, *yh, *yl, *h2h, *h2l, *uh, *ul;
    __nv_bfloat16 *wqh, *wql, *wph, *wpl, *wfh, *wfl, *wmh, *wml;
    cudaGetSymbolAddress((void**)&x1,   g_x1);
    cudaGetSymbolAddress((void**)&qkvh, g_qkvh); cudaGetSymbolAddress((void**)&qkvl, g_qkvl);
    cudaGetSymbolAddress((void**)&hh,  g_hh);  cudaGetSymbolAddress((void**)&hl,  g_hl);
    cudaGetSymbolAddress((void**)&yh,  g_yh);  cudaGetSymbolAddress((void**)&yl,  g_yl);
    cudaGetSymbolAddress((void**)&h2h, g_h2h); cudaGetSymbolAddress((void**)&h2l, g_h2l);
    cudaGetSymbolAddress((void**)&uh,  g_uh);  cudaGetSymbolAddress((void**)&ul,  g_ul);
    cudaGetSymbolAddress((void**)&wqh, g_wqh); cudaGetSymbolAddress((void**)&wql, g_wql);
    cudaGetSymbolAddress((void**)&wph, g_wph); cudaGetSymbolAddress((void**)&wpl, g_wpl);
    cudaGetSymbolAddress((void**)&wfh, g_wfh); cudaGetSymbolAddress((void**)&wfl, g_wfl);
    cudaGetSymbolAddress((void**)&wmh, g_wmh); cudaGetSymbolAddress((void**)&wml, g_wml);

    cudaFuncSetAttribute(attn_mma_kernel,
        cudaFuncAttributeMaxDynamicSharedMemorySize, (int)ATTN_SMEM2);

    // weight transpose + split
    tsplit_kernel<<<dim3(C3_DIM / 32, C_DIM / 32), 256>>>(w_attn, wqh, wql, C_DIM, C3_DIM);
    tsplit_kernel<<<dim3(C_DIM / 32, C_DIM / 32), 256>>>(w_attn_proj, wph, wpl, C_DIM, C_DIM);
    tsplit_kernel<<<dim3(C4_DIM / 32, C_DIM / 32), 256>>>(w_fc, wfh, wfl, C_DIM, C4_DIM);
    tsplit_kernel<<<dim3(C_DIM / 32, C4_DIM / 32), 256>>>(w_mlp_proj, wmh, wml, C4_DIM, C_DIM);

    // 1. LN1 -> bf16 hi/lo
    ln_split_kernel<<<M_ROWS, 256>>>(x, ln1_g, ln1_b, hh, hl);
    // 2. qkv = h @ w_attn + b  -> bf16 hi/lo, Q cols pre-scaled by 1/8
    mm_kernel<4><<<dim3(C3_DIM / 128, M_ROWS / 128), 256>>>(
        hh, hl, wqh, wql, b_attn, nullptr, nullptr, qkvh, qkvl,
        M_ROWS, C3_DIM, C_DIM);
    // 3. attention (tensor-core flash) -> y hi/lo
    attn_mma_kernel<<<dim3(T_SEQ / 128, N_HEAD, 2), 256, ATTN_SMEM2>>>(
        qkvh, qkvl, yh, yl);
    // 4. x1 = x + y @ w_attn_proj + b
    mm_kernel<1><<<dim3(C_DIM / 128, M_ROWS / 128), 256>>>(
        yh, yl, wph, wpl, b_attn_proj, x, x1, nullptr, nullptr,
        M_ROWS, C_DIM, C_DIM);
    // 5. LN2 -> bf16 hi/lo
    ln_split_kernel<<<M_ROWS, 256>>>(x1, ln2_g, ln2_b, h2h, h2l);
    // 6. u = gelu(h2 @ w_fc + b) -> bf16 hi/lo
    mm_kernel<2><<<dim3(C4_DIM / 128, M_ROWS / 128), 256>>>(
        h2h, h2l, wfh, wfl, b_fc, nullptr, nullptr, uh, ul,
        M_ROWS, C4_DIM, C_DIM);
    // 7. out = x1 + u @ w_mlp_proj + b
    mm_kernel<3><<<dim3(C_DIM / 128, M_ROWS / 128), 256>>>(
        uh, ul, wmh, wml, b_mlp_proj, x1, out, nullptr, nullptr,
        M_ROWS, C_DIM, C4_DIM);
}

// round 13
// speedup vs baseline: 2.3974x; 2.3704x over previous
#include <cuda_runtime.h>
#include <cuda_fp16.h>
#include <math.h>
#include <stdint.h>

// ---------------------------------------------------------------------------
// GPT-2 transformer block. GEMMs + attention on mma.sync fp16 single-term
// (fp16 product is exact in fp32 accum; only input-rounding error ~2^-11).
// B=2, T=2048, C=768, H=12, hd=64.  M = B*T = 4096.
// ---------------------------------------------------------------------------

#define M_ROWS 4096
#define C_DIM  768
#define C3_DIM 2304
#define C4_DIM 3072
#define N_HEAD 12
#define HD     64
#define T_SEQ  2048

// ---------------- scratch (device globals) ----------------
__device__ float  g_x1 [M_ROWS * C_DIM];
__device__ __half g_qkv[M_ROWS * C3_DIM];
__device__ __half g_h  [M_ROWS * C_DIM];
__device__ __half g_y  [M_ROWS * C_DIM];
__device__ __half g_h2 [M_ROWS * C_DIM];
__device__ __half g_u  [M_ROWS * C4_DIM];
__device__ __half g_wq [C3_DIM * C_DIM];
__device__ __half g_wp [C_DIM * C_DIM];
__device__ __half g_wf [C4_DIM * C_DIM];
__device__ __half g_wm [C_DIM * C4_DIM];

// ---------------- PTX helpers (base ISA only) ----------
__device__ __forceinline__ uint32_t smem_u32(const void* p) {
    uint32_t a;
    asm("{ .reg .u64 t; cvta.to.shared.u64 t, %1; cvt.u32.u64 %0, t; }"
        : "=r"(a) : "l"(p));
    return a;
}

#define CPA16(dst, src) \
    asm volatile("cp.async.cg.shared.global [%0], [%1], 16;" :: "r"(dst), "l"(src))
#define CP_COMMIT() asm volatile("cp.async.commit_group;" ::: "memory")
#define CP_WAIT1()  asm volatile("cp.async.wait_group 1;" ::: "memory")
#define CP_WAIT0()  asm volatile("cp.async.wait_group 0;" ::: "memory")

#define LDSM_X4(r, addr)                                                       \
    asm volatile("ldmatrix.sync.aligned.m8n8.x4.shared.b16 {%0,%1,%2,%3}, [%4];" \
        : "=r"((r)[0]), "=r"((r)[1]), "=r"((r)[2]), "=r"((r)[3]) : "r"(addr))

#define LDSM_X4_T(r, addr)                                                     \
    asm volatile("ldmatrix.sync.aligned.m8n8.x4.trans.shared.b16 {%0,%1,%2,%3}, [%4];" \
        : "=r"((r)[0]), "=r"((r)[1]), "=r"((r)[2]), "=r"((r)[3]) : "r"(addr))

#define MMA_F16(d, a, b)                                                       \
    asm volatile("mma.sync.aligned.m16n8k16.row.col.f32.f16.f16.f32 "          \
        "{%0,%1,%2,%3}, {%4,%5,%6,%7}, {%8,%9}, {%0,%1,%2,%3};"                \
        : "+f"((d)[0]), "+f"((d)[1]), "+f"((d)[2]), "+f"((d)[3])               \
        : "r"((a)[0]), "r"((a)[1]), "r"((a)[2]), "r"((a)[3]),                  \
          "r"((b)[0]), "r"((b)[1]))

__device__ __forceinline__ float gelu_f(float v) {
    const float c = 0.7978845608028654f;
    return 0.5f * v * (1.0f + tanhf(c * (v + 0.044715f * v * v * v)));
}
__device__ __forceinline__ uint32_t packh2(float a, float b) {
    __half2 h = __floats2half2_rn(a, b);
    return *(uint32_t*)&h;
}

// exp(x) for x <= 0, FMA/ALU pipes only. rel err ~2.4e-6.
__device__ __forceinline__ float fexp(float x) {
    float t = fmaxf(x * 1.4426950408889634f, -126.0f);
    float z = t + 12582912.0f;
    int   e = __float_as_int(z);
    float n = z - 12582912.0f;
    float f = t - n;
    float p =             1.3333558146428443e-3f;
    p = fmaf(p, f,        9.6181291076284772e-3f);
    p = fmaf(p, f,        5.5504108664821580e-2f);
    p = fmaf(p, f,        2.4022650695910071e-1f);
    p = fmaf(p, f,        6.9314718055994531e-1f);
    p = fmaf(p, f,        1.0f);
    return __int_as_float(__float_as_int(p) + (e << 23));
}

// ---------------------------------------------------------------------------
// mma.sync fp16 GEMM: D[M,N] = A[M,K] @ B[N,K]^T + epilogue
// 128x128 CTA tile, 8 warps each 32(M)x64(N), K-chunks of 32, double-buffered.
// EP: 1/3=bias+res->f32  2=bias+gelu->fp16  4=bias, cols<C_DIM x0.125 ->fp16
// ---------------------------------------------------------------------------
template <int EP>
__global__ __launch_bounds__(256)
void mm_kernel(const __half* __restrict__ A, const __half* __restrict__ B,
               const float* __restrict__ bias, const float* __restrict__ res,
               float* __restrict__ outF, __half* __restrict__ outH,
               int M, int N, int K)
{
    __shared__ __half Asm[2][128][40];
    __shared__ __half Bsm[2][128][40];

    int tid = threadIdx.x;
    int wid = tid >> 5, lane = tid & 31;
    int wm = wid & 3, wn = wid >> 2;
    int bm = blockIdx.y, bn = blockIdx.x;

    const int NIT = K / 32;

    uint32_t sA[2] = { smem_u32(&Asm[0][0][0]), smem_u32(&Asm[1][0][0]) };
    uint32_t sB[2] = { smem_u32(&Bsm[0][0][0]), smem_u32(&Bsm[1][0][0]) };

    auto load_chunk = [&](int it2, int b2) {
        int k0 = it2 * 32;
        #pragma unroll
        for (int i = 0; i < 2; i++) {
            int s = tid + i * 256;
            int r = s >> 2, c = s & 3;
            CPA16(sA[b2] + r * 80 + c * 16,
                  (const char*)(A + (size_t)(bm * 128 + r) * K + k0) + c * 16);
            CPA16(sB[b2] + r * 80 + c * 16,
                  (const char*)(B + (size_t)(bn * 128 + r) * K + k0) + c * 16);
        }
    };

    float acc[2][8][4];
    #pragma unroll
    for (int i = 0; i < 2; i++)
        #pragma unroll
        for (int j = 0; j < 8; j++)
            #pragma unroll
            for (int q = 0; q < 4; q++) acc[i][j][q] = 0.f;

    load_chunk(0, 0); CP_COMMIT();
    load_chunk(1, 1); CP_COMMIT();

    int mrow = (lane & 7) + ((lane >> 3) & 1) * 8;
    int kgrp = (lane >> 4) * 8;

    for (int it = 0; it < NIT; ++it) {
        int b = it & 1;
        if (it + 1 < NIT) CP_WAIT1(); else CP_WAIT0();
        __syncthreads();

        #pragma unroll
        for (int ks = 0; ks < 2; ks++) {
            int kcol = ks * 16 + kgrp;
            uint32_t af[2][4], bf[4][4];
            #pragma unroll
            for (int mt = 0; mt < 2; mt++)
                LDSM_X4(af[mt], sA[b] + (wm * 32 + mt * 16 + mrow) * 80 + kcol * 2);
            #pragma unroll
            for (int np = 0; np < 4; np++)
                LDSM_X4(bf[np], sB[b] + (wn * 64 + np * 16 + mrow) * 80 + kcol * 2);
            #pragma unroll
            for (int mt = 0; mt < 2; mt++)
                #pragma unroll
                for (int nt = 0; nt < 8; nt++) {
                    uint32_t bb[2] = { bf[nt >> 1][nt & 1], bf[nt >> 1][(nt & 1) + 2] };
                    MMA_F16(acc[mt][nt], af[mt], bb);
                }
        }
        __syncthreads();
        if (it + 2 < NIT) { load_chunk(it + 2, b); CP_COMMIT(); }
    }

    #pragma unroll
    for (int mt = 0; mt < 2; mt++) {
        int gr0 = bm * 128 + wm * 32 + mt * 16 + (lane >> 2);
        #pragma unroll
        for (int nt = 0; nt < 8; nt++) {
            int gc = bn * 128 + wn * 64 + nt * 8 + (lane & 3) * 2;
            float2 bi = *(const float2*)(bias + gc);
            #pragma unroll
            for (int h = 0; h < 2; h++) {
                int gr = gr0 + h * 8;
                float v0 = acc[mt][nt][h * 2 + 0] + bi.x;
                float v1 = acc[mt][nt][h * 2 + 1] + bi.y;
                size_t o = (size_t)gr * N + gc;
                if (EP == 1 || EP == 3) {
                    float2 rr = *(const float2*)(res + o);
                    v0 += rr.x; v1 += rr.y;
                    float2 ov = {v0, v1};
                    *(float2*)(outF + o) = ov;
                } else {
                    if (EP == 2) { v0 = gelu_f(v0); v1 = gelu_f(v1); }
                    if (EP == 4 && gc < C_DIM) { v0 *= 0.125f; v1 *= 0.125f; }
                    __half2 hv = __floats2half2_rn(v0, v1);
                    *(__half2*)(outH + o) = hv;
                }
            }
        }
    }
}

// ---------------------------------------------------------------------------
// Transpose to fp16:  w[K,N] f32 -> t [N,K] fp16
// ---------------------------------------------------------------------------
__global__ __launch_bounds__(256) void tsplit_kernel(
    const float* __restrict__ w, __half* __restrict__ th, int K, int N)
{
    __shared__ float t[32][33];
    int n0 = blockIdx.x * 32, k0 = blockIdx.y * 32;
    int tx = threadIdx.x & 31, ty = threadIdx.x >> 5;
    #pragma unroll
    for (int j = 0; j < 4; j++) {
        int k = ty + j * 8;
        t[k][tx] = w[(size_t)(k0 + k) * N + n0 + tx];
    }
    __syncthreads();
    #pragma unroll
    for (int j = 0; j < 4; j++) {
        int nn = ty + j * 8;
        th[(size_t)(n0 + nn) * K + k0 + tx] = __float2half_rn(t[tx][nn]);
    }
}

// ---------------------------------------------------------------------------
// LayerNorm -> fp16
// ---------------------------------------------------------------------------
__global__ __launch_bounds__(256) void ln_kernel(
    const float* __restrict__ x, const float* __restrict__ g,
    const float* __restrict__ b, __half* __restrict__ oh)
{
    int row = blockIdx.x;
    int tid = threadIdx.x;
    const float* xr = x + (size_t)row * C_DIM;

    float v0 = xr[tid], v1 = xr[tid + 256], v2 = xr[tid + 512];
    float s = v0 + v1 + v2;
    float sq = v0 * v0 + v1 * v1 + v2 * v2;
    #pragma unroll
    for (int o = 16; o > 0; o >>= 1) {
        s  += __shfl_xor_sync(0xffffffffu, s,  o);
        sq += __shfl_xor_sync(0xffffffffu, sq, o);
    }
    __shared__ float ss[8], sqs[8];
    int wid = tid >> 5, lane = tid & 31;
    if (lane == 0) { ss[wid] = s; sqs[wid] = sq; }
    __syncthreads();
    s = 0.f; sq = 0.f;
    #pragma unroll
    for (int i = 0; i < 8; i++) { s += ss[i]; sq += sqs[i]; }

    float mu = s * (1.0f / C_DIM);
    float var = sq * (1.0f / C_DIM) - mu * mu;
    float inv = rsqrtf(var + 1e-5f);

    size_t base = (size_t)row * C_DIM;
    #pragma unroll
    for (int e = 0; e < 3; e++) {
        int idx = tid + e * 256;
        float val = ((e == 0 ? v0 : e == 1 ? v1 : v2) - mu) * inv * g[idx] + b[idx];
        oh[base + idx] = __float2half_rn(val);
    }
}

// ---------------------------------------------------------------------------
// Flash attention on mma.sync fp16 single-term. Pre-scaled fp16 qkv in gmem,
// cp.async double-buffered K/V, Q frags register-hoisted, FMA-pipe exp.
// smem = Q 18KB + 2x(K 9KB + V 9KB) = 54KB -> 2 CTAs/SM.
// CTA: 128 queries x (head, batch); 8 warps x 16 rows.
// ---------------------------------------------------------------------------
#define ASTR 72
#define QBUF (128 * ASTR)
#define KVB  (64 * ASTR)
#define ATTN_SMEM2 (size_t)((QBUF + 4 * KVB) * sizeof(__half))

__global__ __launch_bounds__(256, 2) void attn_mma_kernel(
    const __half* __restrict__ qkv,
    __half* __restrict__ y)
{
    extern __shared__ __half smh[];
    uint32_t sQ = smem_u32(smh);
    uint32_t sK[2], sV[2];
    sK[0] = sQ + QBUF * 2;
    sV[0] = sK[0] + KVB * 2;
    sK[1] = sV[0] + KVB * 2;
    sV[1] = sK[1] + KVB * 2;

    int qt = gridDim.x - 1 - blockIdx.x;   // heavy tiles first
    int hh = blockIdx.y, bb = blockIdx.z;
    int tid = threadIdx.x, wid = tid >> 5, lane = tid & 31;

    int mrow = (lane & 7) + ((lane >> 3) & 1) * 8;
    int kgrp = (lane >> 4) * 8;

    auto load_kv = [&](int kt, int b2) {
        #pragma unroll
        for (int i = 0; i < 4; i++) {
            int s = tid + i * 256;          // 0..1023
            int arr = s >> 9;               // 0=K 1=V
            int rem = s & 511;
            int r = rem >> 3, c = rem & 7;
            int colb = ((arr == 0) ? C_DIM : 2 * C_DIM) + hh * HD;
            const __half* src = qkv
                + (size_t)(bb * T_SEQ + kt * 64 + r) * C3_DIM + colb + c * 8;
            CPA16((arr ? sV[b2] : sK[b2]) + (r * ASTR + c * 8) * 2, src);
        }
    };

    // group 0: Q tile (128 x 64 fp16)
    #pragma unroll
    for (int i = 0; i < 4; i++) {
        int s = tid + i * 256;              // 0..1023
        int r = s >> 3, c = s & 7;
        const __half* src = qkv
            + (size_t)(bb * T_SEQ + qt * 128 + r) * C3_DIM + hh * HD + c * 8;
        CPA16(sQ + (r * ASTR + c * 8) * 2, src);
    }
    CP_COMMIT();
    load_kv(0, 0); CP_COMMIT();             // group 1: KV tile 0

    CP_WAIT1();                             // Q complete
    __syncthreads();

    uint32_t qf[4][4];
    #pragma unroll
    for (int kc = 0; kc < 4; kc++) {
        uint32_t aoff = ((wid * 16 + mrow) * ASTR + kc * 16 + kgrp) * 2;
        LDSM_X4(qf[kc], sQ + aoff);
    }

    float m0 = -1e30f, m1 = -1e30f, l0 = 0.f, l1 = 0.f;
    float oacc[8][4];
    #pragma unroll
    for (int i = 0; i < 8; i++)
        #pragma unroll
        for (int j = 0; j < 4; j++) oacc[i][j] = 0.f;

    int nkt = 2 * qt + 2;
    for (int kt = 0; kt < nkt; kt++) {
        int b = kt & 1;
        if (kt + 1 < nkt) { load_kv(kt + 1, b ^ 1); CP_COMMIT(); CP_WAIT1(); }
        else CP_WAIT0();
        __syncthreads();

        // ---- S = Q @ K^T (single fp16 term) ----
        float sacc[8][4];
        #pragma unroll
        for (int i = 0; i < 8; i++)
            #pragma unroll
            for (int j = 0; j < 4; j++) sacc[i][j] = 0.f;

        #pragma unroll
        for (int kc = 0; kc < 4; kc++) {
            #pragma unroll
            for (int ng = 0; ng < 4; ng++) {
                uint32_t bh[4];
                uint32_t boff = ((ng * 16 + mrow) * ASTR + kc * 16 + kgrp) * 2;
                LDSM_X4(bh, sK[b] + boff);
                #pragma unroll
                for (int t = 0; t < 2; t++) {
                    uint32_t b0[2] = { bh[t], bh[t + 2] };
                    MMA_F16(sacc[ng * 2 + t], qf[kc], b0);
                }
            }
        }

        // ---- causal mask ----
        int g0 = qt * 128 + wid * 16 + (lane >> 2);
        if (kt * 64 + 63 > qt * 128 + wid * 16) {
            #pragma unroll
            for (int nt = 0; nt < 8; nt++) {
                int kc0 = kt * 64 + nt * 8 + (lane & 3) * 2;
                if (kc0     > g0)     sacc[nt][0] = -1e30f;
                if (kc0 + 1 > g0)     sacc[nt][1] = -1e30f;
                if (kc0     > g0 + 8) sacc[nt][2] = -1e30f;
                if (kc0 + 1 > g0 + 8) sacc[nt][3] = -1e30f;
            }
        }

        // ---- online softmax (FMA-pipe exp) ----
        float mt0 = -1e30f, mt1 = -1e30f;
        #pragma unroll
        for (int nt = 0; nt < 8; nt++) {
            mt0 = fmaxf(mt0, fmaxf(sacc[nt][0], sacc[nt][1]));
            mt1 = fmaxf(mt1, fmaxf(sacc[nt][2], sacc[nt][3]));
        }
        mt0 = fmaxf(mt0, __shfl_xor_sync(0xffffffffu, mt0, 1));
        mt0 = fmaxf(mt0, __shfl_xor_sync(0xffffffffu, mt0, 2));
        mt1 = fmaxf(mt1, __shfl_xor_sync(0xffffffffu, mt1, 1));
        mt1 = fmaxf(mt1, __shfl_xor_sync(0xffffffffu, mt1, 2));

        float mn0 = fmaxf(m0, mt0), mn1 = fmaxf(m1, mt1);
        float c0 = fexp(m0 - mn0), c1 = fexp(m1 - mn1);
        m0 = mn0; m1 = mn1;

        float ps0 = 0.f, ps1 = 0.f;
        #pragma unroll
        for (int nt = 0; nt < 8; nt++) {
            sacc[nt][0] = fexp(sacc[nt][0] - m0);
            sacc[nt][1] = fexp(sacc[nt][1] - m0);
            sacc[nt][2] = fexp(sacc[nt][2] - m1);
            sacc[nt][3] = fexp(sacc[nt][3] - m1);
            ps0 += sacc[nt][0] + sacc[nt][1];
            ps1 += sacc[nt][2] + sacc[nt][3];
        }
        ps0 += __shfl_xor_sync(0xffffffffu, ps0, 1);
        ps0 += __shfl_xor_sync(0xffffffffu, ps0, 2);
        ps1 += __shfl_xor_sync(0xffffffffu, ps1, 1);
        ps1 += __shfl_xor_sync(0xffffffffu, ps1, 2);
        l0 = l0 * c0 + ps0;
        l1 = l1 * c1 + ps1;
        #pragma unroll
        for (int dt = 0; dt < 8; dt++) {
            oacc[dt][0] *= c0; oacc[dt][1] *= c0;
            oacc[dt][2] *= c1; oacc[dt][3] *= c1;
        }

        // ---- O += P @ V (single fp16 term), P frags in-register ----
        #pragma unroll
        for (int kc = 0; kc < 4; kc++) {
            uint32_t ah[4];
            ah[0] = packh2(sacc[2 * kc][0],     sacc[2 * kc][1]);
            ah[1] = packh2(sacc[2 * kc][2],     sacc[2 * kc][3]);
            ah[2] = packh2(sacc[2 * kc + 1][0], sacc[2 * kc + 1][1]);
            ah[3] = packh2(sacc[2 * kc + 1][2], sacc[2 * kc + 1][3]);
            #pragma unroll
            for (int ng = 0; ng < 4; ng++) {
                uint32_t bv[4];
                uint32_t voff = ((kc * 16 + ((lane >> 3) & 1) * 8 + (lane & 7)) * ASTR
                                 + ng * 16 + (lane >> 4) * 8) * 2;
                LDSM_X4_T(bv, sV[b] + voff);
                #pragma unroll
                for (int t = 0; t < 2; t++) {
                    uint32_t b0[2] = { bv[2 * t], bv[2 * t + 1] };
                    MMA_F16(oacc[ng * 2 + t], ah, b0);
                }
            }
        }
        __syncthreads();   // all warps done with buffer b before refill
    }

    // ---- epilogue: normalize, store fp16 ----
    float i0 = 1.0f / l0, i1 = 1.0f / l1;
    int gr0 = qt * 128 + wid * 16 + (lane >> 2);
    #pragma unroll
    for (int dt = 0; dt < 8; dt++) {
        int col = hh * HD + dt * 8 + (lane & 3) * 2;
        size_t o0 = ((size_t)(bb * T_SEQ + gr0)) * C_DIM + col;
        size_t o1 = ((size_t)(bb * T_SEQ + gr0 + 8)) * C_DIM + col;
        *(__half2*)(y + o0) = __floats2half2_rn(oacc[dt][0] * i0, oacc[dt][1] * i0);
        *(__half2*)(y + o1) = __floats2half2_rn(oacc[dt][2] * i1, oacc[dt][3] * i1);
    }
}

// ---------------------------------------------------------------------------
// Launch
// ---------------------------------------------------------------------------
extern "C" void kernel_launch(void* const* d_in, const int* in_sizes, int n_in,
                              void* d_out, int out_size)
{
    const float* x           = (const float*)d_in[0];
    const float* ln1_g       = (const float*)d_in[1];
    const float* ln1_b       = (const float*)d_in[2];
    const float* w_attn      = (const float*)d_in[3];
    const float* b_attn      = (const float*)d_in[4];
    const float* w_attn_proj = (const float*)d_in[5];
    const float* b_attn_proj = (const float*)d_in[6];
    const float* ln2_g       = (const float*)d_in[7];
    const float* ln2_b       = (const float*)d_in[8];
    const float* w_fc        = (const float*)d_in[9];
    const float* b_fc        = (const float*)d_in[10];
    const float* w_mlp_proj  = (const float*)d_in[11];
    const float* b_mlp_proj  = (const float*)d_in[12];
    float* out = (float*)d_out;

    float *x1;
    __half *qkv, *h, *y, *h2, *u, *wq, *wp, *wf, *wm;
    cudaGetSymbolAddress((void**)&x1,  g_x1);
    cudaGetSymbolAddress((void**)&qkv, g_qkv);
    cudaGetSymbolAddress((void**)&h,   g_h);
    cudaGetSymbolAddress((void**)&y,   g_y);
    cudaGetSymbolAddress((void**)&h2,  g_h2);
    cudaGetSymbolAddress((void**)&u,   g_u);
    cudaGetSymbolAddress((void**)&wq,  g_wq);
    cudaGetSymbolAddress((void**)&wp,  g_wp);
    cudaGetSymbolAddress((void**)&wf,  g_wf);
    cudaGetSymbolAddress((void**)&wm,  g_wm);

    cudaFuncSetAttribute(attn_mma_kernel,
        cudaFuncAttributeMaxDynamicSharedMemorySize, (int)ATTN_SMEM2);

    // weight transpose -> fp16
    tsplit_kernel<<<dim3(C3_DIM / 32, C_DIM / 32), 256>>>(w_attn, wq, C_DIM, C3_DIM);
    tsplit_kernel<<<dim3(C_DIM / 32, C_DIM / 32), 256>>>(w_attn_proj, wp, C_DIM, C_DIM);
    tsplit_kernel<<<dim3(C4_DIM / 32, C_DIM / 32), 256>>>(w_fc, wf, C_DIM, C4_DIM);
    tsplit_kernel<<<dim3(C_DIM / 32, C4_DIM / 32), 256>>>(w_mlp_proj, wm, C4_DIM, C_DIM);

    // 1. LN1 -> fp16
    ln_kernel<<<M_ROWS, 256>>>(x, ln1_g, ln1_b, h);
    // 2. qkv = h @ w_attn + b  -> fp16, Q cols pre-scaled by 1/8
    mm_kernel<4><<<dim3(C3_DIM / 128, M_ROWS / 128), 256>>>(
        h, wq, b_attn, nullptr, nullptr, qkv, M_ROWS, C3_DIM, C_DIM);
    // 3. attention (tensor-core flash) -> y fp16
    attn_mma_kernel<<<dim3(T_SEQ / 128, N_HEAD, 2), 256, ATTN_SMEM2>>>(qkv, y);
    // 4. x1 = x + y @ w_attn_proj + b
    mm_kernel<1><<<dim3(C_DIM / 128, M_ROWS / 128), 256>>>(
        y, wp, b_attn_proj, x, x1, nullptr, M_ROWS, C_DIM, C_DIM);
    // 5. LN2 -> fp16
    ln_kernel<<<M_ROWS, 256>>>(x1, ln2_g, ln2_b, h2);
    // 6. u = gelu(h2 @ w_fc + b) -> fp16
    mm_kernel<2><<<dim3(C4_DIM / 128, M_ROWS / 128), 256>>>(
        h2, wf, b_fc, nullptr, nullptr, u, M_ROWS, C4_DIM, C_DIM);
    // 7. out = x1 + u @ w_mlp_proj + b
    mm_kernel<3><<<dim3(C_DIM / 128, M_ROWS / 128), 256>>>(
        u, wm, b_mlp_proj, x1, out, nullptr, M_ROWS, C_DIM, C4_DIM);
}

// round 14
// speedup vs baseline: 2.4085x; 1.0047x over previous
#include <cuda_runtime.h>
#include <cuda_fp16.h>
#include <math.h>
#include <stdint.h>

// ---------------------------------------------------------------------------
// GPT-2 transformer block. GEMMs + attention on mma.sync fp16 single-term.
// 3-stage cp.async pipelines, single sync per mainloop iteration.
// B=2, T=2048, C=768, H=12, hd=64.  M = B*T = 4096.
// ---------------------------------------------------------------------------

#define M_ROWS 4096
#define C_DIM  768
#define C3_DIM 2304
#define C4_DIM 3072
#define N_HEAD 12
#define HD     64
#define T_SEQ  2048

// ---------------- scratch (device globals) ----------------
__device__ float  g_x1 [M_ROWS * C_DIM];
__device__ __half g_qkv[M_ROWS * C3_DIM];
__device__ __half g_h  [M_ROWS * C_DIM];
__device__ __half g_y  [M_ROWS * C_DIM];
__device__ __half g_h2 [M_ROWS * C_DIM];
__device__ __half g_u  [M_ROWS * C4_DIM];
__device__ __half g_wq [C3_DIM * C_DIM];
__device__ __half g_wp [C_DIM * C_DIM];
__device__ __half g_wf [C4_DIM * C_DIM];
__device__ __half g_wm [C_DIM * C4_DIM];

// ---------------- PTX helpers (base ISA only) ----------
__device__ __forceinline__ uint32_t smem_u32(const void* p) {
    uint32_t a;
    asm("{ .reg .u64 t; cvta.to.shared.u64 t, %1; cvt.u32.u64 %0, t; }"
        : "=r"(a) : "l"(p));
    return a;
}

#define CPA16(dst, src) \
    asm volatile("cp.async.cg.shared.global [%0], [%1], 16;" :: "r"(dst), "l"(src))
#define CP_COMMIT() asm volatile("cp.async.commit_group;" ::: "memory")
#define CP_WAIT2()  asm volatile("cp.async.wait_group 2;" ::: "memory")
#define CP_WAIT1()  asm volatile("cp.async.wait_group 1;" ::: "memory")
#define CP_WAIT0()  asm volatile("cp.async.wait_group 0;" ::: "memory")

#define LDSM_X4(r, addr)                                                       \
    asm volatile("ldmatrix.sync.aligned.m8n8.x4.shared.b16 {%0,%1,%2,%3}, [%4];" \
        : "=r"((r)[0]), "=r"((r)[1]), "=r"((r)[2]), "=r"((r)[3]) : "r"(addr))

#define LDSM_X4_T(r, addr)                                                     \
    asm volatile("ldmatrix.sync.aligned.m8n8.x4.trans.shared.b16 {%0,%1,%2,%3}, [%4];" \
        : "=r"((r)[0]), "=r"((r)[1]), "=r"((r)[2]), "=r"((r)[3]) : "r"(addr))

#define MMA_F16(d, a, b)                                                       \
    asm volatile("mma.sync.aligned.m16n8k16.row.col.f32.f16.f16.f32 "          \
        "{%0,%1,%2,%3}, {%4,%5,%6,%7}, {%8,%9}, {%0,%1,%2,%3};"                \
        : "+f"((d)[0]), "+f"((d)[1]), "+f"((d)[2]), "+f"((d)[3])               \
        : "r"((a)[0]), "r"((a)[1]), "r"((a)[2]), "r"((a)[3]),                  \
          "r"((b)[0]), "r"((b)[1]))

__device__ __forceinline__ float gelu_f(float v) {
    const float c = 0.7978845608028654f;
    return 0.5f * v * (1.0f + tanhf(c * (v + 0.044715f * v * v * v)));
}
__device__ __forceinline__ uint32_t packh2(float a, float b) {
    __half2 h = __floats2half2_rn(a, b);
    return *(uint32_t*)&h;
}

// exp(x) for x <= 0, FMA/ALU pipes only. rel err ~2.4e-6.
__device__ __forceinline__ float fexp(float x) {
    float t = fmaxf(x * 1.4426950408889634f, -126.0f);
    float z = t + 12582912.0f;
    int   e = __float_as_int(z);
    float n = z - 12582912.0f;
    float f = t - n;
    float p =             1.3333558146428443e-3f;
    p = fmaf(p, f,        9.6181291076284772e-3f);
    p = fmaf(p, f,        5.5504108664821580e-2f);
    p = fmaf(p, f,        2.4022650695910071e-1f);
    p = fmaf(p, f,        6.9314718055994531e-1f);
    p = fmaf(p, f,        1.0f);
    return __int_as_float(__float_as_int(p) + (e << 23));
}

// ---------------------------------------------------------------------------
// mma.sync fp16 GEMM: D[M,N] = A[M,K] @ B[N,K]^T + epilogue
// 128x128 CTA tile, 8 warps each 32(M)x64(N), K-chunks of 32.
// 3-stage cp.async ring, ONE __syncthreads per iteration.
// EP: 1/3=bias+res->f32  2=bias+gelu->fp16  4=bias, cols<C_DIM x0.125 ->fp16
// ---------------------------------------------------------------------------
#define MMBUF 5120                    // halves per (A or B) buffer: 128*40
#define MM_SMEM (size_t)(6 * MMBUF * sizeof(__half))   // 61440 B

template <int EP>
__global__ __launch_bounds__(256)
void mm_kernel(const __half* __restrict__ A, const __half* __restrict__ B,
               const float* __restrict__ bias, const float* __restrict__ res,
               float* __restrict__ outF, __half* __restrict__ outH,
               int M, int N, int K)
{
    extern __shared__ __half mmsm[];
    uint32_t base = smem_u32(mmsm);
    uint32_t sA[3], sB[3];
    #pragma unroll
    for (int i = 0; i < 3; i++) {
        sA[i] = base + i * MMBUF * 2;
        sB[i] = base + (3 + i) * MMBUF * 2;
    }

    int tid = threadIdx.x;
    int wid = tid >> 5, lane = tid & 31;
    int wm = wid & 3, wn = wid >> 2;
    int bm = blockIdx.y, bn = blockIdx.x;

    const int NIT = K / 32;

    auto load_chunk = [&](int it2, int b2) {
        int k0 = it2 * 32;
        #pragma unroll
        for (int i = 0; i < 2; i++) {
            int s = tid + i * 256;
            int r = s >> 2, c = s & 3;
            CPA16(sA[b2] + r * 80 + c * 16,
                  (const char*)(A + (size_t)(bm * 128 + r) * K + k0) + c * 16);
            CPA16(sB[b2] + r * 80 + c * 16,
                  (const char*)(B + (size_t)(bn * 128 + r) * K + k0) + c * 16);
        }
    };

    float acc[2][8][4];
    #pragma unroll
    for (int i = 0; i < 2; i++)
        #pragma unroll
        for (int j = 0; j < 8; j++)
            #pragma unroll
            for (int q = 0; q < 4; q++) acc[i][j][q] = 0.f;

    load_chunk(0, 0); CP_COMMIT();
    load_chunk(1, 1); CP_COMMIT();

    int mrow = (lane & 7) + ((lane >> 3) & 1) * 8;
    int kgrp = (lane >> 4) * 8;

    for (int it = 0; it < NIT; ++it) {
        int b = it % 3;
        if (it + 1 < NIT) CP_WAIT1(); else CP_WAIT0();
        __syncthreads();                       // data ready + prev-iter reads done
        if (it + 2 < NIT) { load_chunk(it + 2, (it + 2) % 3); CP_COMMIT(); }

        #pragma unroll
        for (int ks = 0; ks < 2; ks++) {
            int kcol = ks * 16 + kgrp;
            uint32_t af[2][4], bf[4][4];
            #pragma unroll
            for (int mt = 0; mt < 2; mt++)
                LDSM_X4(af[mt], sA[b] + ((wm * 32 + mt * 16 + mrow) * 80 + kcol * 2));
            #pragma unroll
            for (int np = 0; np < 4; np++)
                LDSM_X4(bf[np], sB[b] + ((wn * 64 + np * 16 + mrow) * 80 + kcol * 2));
            #pragma unroll
            for (int mt = 0; mt < 2; mt++)
                #pragma unroll
                for (int nt = 0; nt < 8; nt++) {
                    uint32_t bb[2] = { bf[nt >> 1][nt & 1], bf[nt >> 1][(nt & 1) + 2] };
                    MMA_F16(acc[mt][nt], af[mt], bb);
                }
        }
    }

    #pragma unroll
    for (int mt = 0; mt < 2; mt++) {
        int gr0 = bm * 128 + wm * 32 + mt * 16 + (lane >> 2);
        #pragma unroll
        for (int nt = 0; nt < 8; nt++) {
            int gc = bn * 128 + wn * 64 + nt * 8 + (lane & 3) * 2;
            float2 bi = *(const float2*)(bias + gc);
            #pragma unroll
            for (int h = 0; h < 2; h++) {
                int gr = gr0 + h * 8;
                float v0 = acc[mt][nt][h * 2 + 0] + bi.x;
                float v1 = acc[mt][nt][h * 2 + 1] + bi.y;
                size_t o = (size_t)gr * N + gc;
                if (EP == 1 || EP == 3) {
                    float2 rr = *(const float2*)(res + o);
                    v0 += rr.x; v1 += rr.y;
                    float2 ov = {v0, v1};
                    *(float2*)(outF + o) = ov;
                } else {
                    if (EP == 2) { v0 = gelu_f(v0); v1 = gelu_f(v1); }
                    if (EP == 4 && gc < C_DIM) { v0 *= 0.125f; v1 *= 0.125f; }
                    __half2 hv = __floats2half2_rn(v0, v1);
                    *(__half2*)(outH + o) = hv;
                }
            }
        }
    }
}

// ---------------------------------------------------------------------------
// All 4 weight transposes (f32 [K,N] -> fp16 [N,K]) in ONE launch.
// Block ranges: wq 1728 | wp 576 | wf 2304 | wm 2304  (total 6912)
// ---------------------------------------------------------------------------
__global__ __launch_bounds__(256) void tsplit_all(
    const float* __restrict__ w0, __half* __restrict__ t0,
    const float* __restrict__ w1, __half* __restrict__ t1,
    const float* __restrict__ w2, __half* __restrict__ t2,
    const float* __restrict__ w3, __half* __restrict__ t3)
{
    int bid = blockIdx.x;
    const float* w; __half* th; int K, N, lb;
    if (bid < 1728)      { w = w0; th = t0; K = 768;  N = 2304; lb = bid; }
    else if (bid < 2304) { w = w1; th = t1; K = 768;  N = 768;  lb = bid - 1728; }
    else if (bid < 4608) { w = w2; th = t2; K = 768;  N = 3072; lb = bid - 2304; }
    else                 { w = w3; th = t3; K = 3072; N = 768;  lb = bid - 4608; }

    __shared__ float t[32][33];
    int nb = N >> 5;
    int n0 = (lb % nb) * 32, k0 = (lb / nb) * 32;
    int tx = threadIdx.x & 31, ty = threadIdx.x >> 5;
    #pragma unroll
    for (int j = 0; j < 4; j++) {
        int k = ty + j * 8;
        t[k][tx] = w[(size_t)(k0 + k) * N + n0 + tx];
    }
    __syncthreads();
    #pragma unroll
    for (int j = 0; j < 4; j++) {
        int nn = ty + j * 8;
        th[(size_t)(n0 + nn) * K + k0 + tx] = __float2half_rn(t[tx][nn]);
    }
}

// ---------------------------------------------------------------------------
// LayerNorm -> fp16
// ---------------------------------------------------------------------------
__global__ __launch_bounds__(256) void ln_kernel(
    const float* __restrict__ x, const float* __restrict__ g,
    const float* __restrict__ b, __half* __restrict__ oh)
{
    int row = blockIdx.x;
    int tid = threadIdx.x;
    const float* xr = x + (size_t)row * C_DIM;

    float v0 = xr[tid], v1 = xr[tid + 256], v2 = xr[tid + 512];
    float s = v0 + v1 + v2;
    float sq = v0 * v0 + v1 * v1 + v2 * v2;
    #pragma unroll
    for (int o = 16; o > 0; o >>= 1) {
        s  += __shfl_xor_sync(0xffffffffu, s,  o);
        sq += __shfl_xor_sync(0xffffffffu, sq, o);
    }
    __shared__ float ss[8], sqs[8];
    int wid = tid >> 5, lane = tid & 31;
    if (lane == 0) { ss[wid] = s; sqs[wid] = sq; }
    __syncthreads();
    s = 0.f; sq = 0.f;
    #pragma unroll
    for (int i = 0; i < 8; i++) { s += ss[i]; sq += sqs[i]; }

    float mu = s * (1.0f / C_DIM);
    float var = sq * (1.0f / C_DIM) - mu * mu;
    float inv = rsqrtf(var + 1e-5f);

    size_t base = (size_t)row * C_DIM;
    #pragma unroll
    for (int e = 0; e < 3; e++) {
        int idx = tid + e * 256;
        float val = ((e == 0 ? v0 : e == 1 ? v1 : v2) - mu) * inv * g[idx] + b[idx];
        oh[base + idx] = __float2half_rn(val);
    }
}

// ---------------------------------------------------------------------------
// Flash attention on mma.sync fp16 single-term. 3-buffer K/V ring, ONE sync
// per iteration. Q separate (18KB); smem total 72KB -> 2 CTAs/SM.
// CTA: 128 queries x (head, batch); 8 warps x 16 rows.
// ---------------------------------------------------------------------------
#define ASTR 72
#define QBUF (128 * ASTR)
#define KVB  (64 * ASTR)
#define ATTN_SMEM2 (size_t)((QBUF + 6 * KVB) * sizeof(__half))

__global__ __launch_bounds__(256, 2) void attn_mma_kernel(
    const __half* __restrict__ qkv,
    __half* __restrict__ y)
{
    extern __shared__ __half smh[];
    uint32_t sQ = smem_u32(smh);
    uint32_t sK[3], sV[3];
    #pragma unroll
    for (int i = 0; i < 3; i++) {
        sK[i] = sQ + (QBUF + 2 * i * KVB) * 2;
        sV[i] = sK[i] + KVB * 2;
    }

    int qt = gridDim.x - 1 - blockIdx.x;   // heavy tiles first
    int hh = blockIdx.y, bb = blockIdx.z;
    int tid = threadIdx.x, wid = tid >> 5, lane = tid & 31;

    int mrow = (lane & 7) + ((lane >> 3) & 1) * 8;
    int kgrp = (lane >> 4) * 8;

    auto load_kv = [&](int kt, int b2) {
        #pragma unroll
        for (int i = 0; i < 4; i++) {
            int s = tid + i * 256;          // 0..1023
            int arr = s >> 9;               // 0=K 1=V
            int rem = s & 511;
            int r = rem >> 3, c = rem & 7;
            int colb = ((arr == 0) ? C_DIM : 2 * C_DIM) + hh * HD;
            const __half* src = qkv
                + (size_t)(bb * T_SEQ + kt * 64 + r) * C3_DIM + colb + c * 8;
            CPA16((arr ? sV[b2] : sK[b2]) + (r * ASTR + c * 8) * 2, src);
        }
    };

    // group 0: Q tile (128 x 64 fp16)
    #pragma unroll
    for (int i = 0; i < 4; i++) {
        int s = tid + i * 256;              // 0..1023
        int r = s >> 3, c = s & 7;
        const __half* src = qkv
            + (size_t)(bb * T_SEQ + qt * 128 + r) * C3_DIM + hh * HD + c * 8;
        CPA16(sQ + (r * ASTR + c * 8) * 2, src);
    }
    CP_COMMIT();
    load_kv(0, 0); CP_COMMIT();             // group 1
    load_kv(1, 1); CP_COMMIT();             // group 2  (nkt >= 2 always)

    CP_WAIT2();                             // Q complete
    __syncthreads();

    uint32_t qf[4][4];
    #pragma unroll
    for (int kc = 0; kc < 4; kc++) {
        uint32_t aoff = ((wid * 16 + mrow) * ASTR + kc * 16 + kgrp) * 2;
        LDSM_X4(qf[kc], sQ + aoff);
    }

    float m0 = -1e30f, m1 = -1e30f, l0 = 0.f, l1 = 0.f;
    float oacc[8][4];
    #pragma unroll
    for (int i = 0; i < 8; i++)
        #pragma unroll
        for (int j = 0; j < 4; j++) oacc[i][j] = 0.f;

    int nkt = 2 * qt + 2;
    for (int kt = 0; kt < nkt; kt++) {
        int b = kt % 3;
        if (kt + 1 < nkt) CP_WAIT1(); else CP_WAIT0();
        __syncthreads();                    // kv_kt ready + prev-iter reads done
        if (kt + 2 < nkt) { load_kv(kt + 2, (kt + 2) % 3); CP_COMMIT(); }

        // ---- S = Q @ K^T (single fp16 term) ----
        float sacc[8][4];
        #pragma unroll
        for (int i = 0; i < 8; i++)
            #pragma unroll
            for (int j = 0; j < 4; j++) sacc[i][j] = 0.f;

        #pragma unroll
        for (int kc = 0; kc < 4; kc++) {
            #pragma unroll
            for (int ng = 0; ng < 4; ng++) {
                uint32_t bh[4];
                uint32_t boff = ((ng * 16 + mrow) * ASTR + kc * 16 + kgrp) * 2;
                LDSM_X4(bh, sK[b] + boff);
                #pragma unroll
                for (int t = 0; t < 2; t++) {
                    uint32_t b0[2] = { bh[t], bh[t + 2] };
                    MMA_F16(sacc[ng * 2 + t], qf[kc], b0);
                }
            }
        }

        // ---- causal mask ----
        int g0 = qt * 128 + wid * 16 + (lane >> 2);
        if (kt * 64 + 63 > qt * 128 + wid * 16) {
            #pragma unroll
            for (int nt = 0; nt < 8; nt++) {
                int kc0 = kt * 64 + nt * 8 + (lane & 3) * 2;
                if (kc0     > g0)     sacc[nt][0] = -1e30f;
                if (kc0 + 1 > g0)     sacc[nt][1] = -1e30f;
                if (kc0     > g0 + 8) sacc[nt][2] = -1e30f;
                if (kc0 + 1 > g0 + 8) sacc[nt][3] = -1e30f;
            }
        }

        // ---- online softmax (FMA-pipe exp) ----
        float mt0 = -1e30f, mt1 = -1e30f;
        #pragma unroll
        for (int nt = 0; nt < 8; nt++) {
            mt0 = fmaxf(mt0, fmaxf(sacc[nt][0], sacc[nt][1]));
            mt1 = fmaxf(mt1, fmaxf(sacc[nt][2], sacc[nt][3]));
        }
        mt0 = fmaxf(mt0, __shfl_xor_sync(0xffffffffu, mt0, 1));
        mt0 = fmaxf(mt0, __shfl_xor_sync(0xffffffffu, mt0, 2));
        mt1 = fmaxf(mt1, __shfl_xor_sync(0xffffffffu, mt1, 1));
        mt1 = fmaxf(mt1, __shfl_xor_sync(0xffffffffu, mt1, 2));

        float mn0 = fmaxf(m0, mt0), mn1 = fmaxf(m1, mt1);
        float c0 = fexp(m0 - mn0), c1 = fexp(m1 - mn1);
        m0 = mn0; m1 = mn1;

        float ps0 = 0.f, ps1 = 0.f;
        #pragma unroll
        for (int nt = 0; nt < 8; nt++) {
            sacc[nt][0] = fexp(sacc[nt][0] - m0);
            sacc[nt][1] = fexp(sacc[nt][1] - m0);
            sacc[nt][2] = fexp(sacc[nt][2] - m1);
            sacc[nt][3] = fexp(sacc[nt][3] - m1);
            ps0 += sacc[nt][0] + sacc[nt][1];
            ps1 += sacc[nt][2] + sacc[nt][3];
        }
        ps0 += __shfl_xor_sync(0xffffffffu, ps0, 1);
        ps0 += __shfl_xor_sync(0xffffffffu, ps0, 2);
        ps1 += __shfl_xor_sync(0xffffffffu, ps1, 1);
        ps1 += __shfl_xor_sync(0xffffffffu, ps1, 2);
        l0 = l0 * c0 + ps0;
        l1 = l1 * c1 + ps1;
        #pragma unroll
        for (int dt = 0; dt < 8; dt++) {
            oacc[dt][0] *= c0; oacc[dt][1] *= c0;
            oacc[dt][2] *= c1; oacc[dt][3] *= c1;
        }

        // ---- O += P @ V (single fp16 term), P frags in-register ----
        #pragma unroll
        for (int kc = 0; kc < 4; kc++) {
            uint32_t ah[4];
            ah[0] = packh2(sacc[2 * kc][0],     sacc[2 * kc][1]);
            ah[1] = packh2(sacc[2 * kc][2],     sacc[2 * kc][3]);
            ah[2] = packh2(sacc[2 * kc + 1][0], sacc[2 * kc + 1][1]);
            ah[3] = packh2(sacc[2 * kc + 1][2], sacc[2 * kc + 1][3]);
            #pragma unroll
            for (int ng = 0; ng < 4; ng++) {
                uint32_t bv[4];
                uint32_t voff = ((kc * 16 + ((lane >> 3) & 1) * 8 + (lane & 7)) * ASTR
                                 + ng * 16 + (lane >> 4) * 8) * 2;
                LDSM_X4_T(bv, sV[b] + voff);
                #pragma unroll
                for (int t = 0; t < 2; t++) {
                    uint32_t b0[2] = { bv[2 * t], bv[2 * t + 1] };
                    MMA_F16(oacc[ng * 2 + t], ah, b0);
                }
            }
        }
    }

    // ---- epilogue: normalize, store fp16 ----
    float i0 = 1.0f / l0, i1 = 1.0f / l1;
    int gr0 = qt * 128 + wid * 16 + (lane >> 2);
    #pragma unroll
    for (int dt = 0; dt < 8; dt++) {
        int col = hh * HD + dt * 8 + (lane & 3) * 2;
        size_t o0 = ((size_t)(bb * T_SEQ + gr0)) * C_DIM + col;
        size_t o1 = ((size_t)(bb * T_SEQ + gr0 + 8)) * C_DIM + col;
        *(__half2*)(y + o0) = __floats2half2_rn(oacc[dt][0] * i0, oacc[dt][1] * i0);
        *(__half2*)(y + o1) = __floats2half2_rn(oacc[dt][2] * i1, oacc[dt][3] * i1);
    }
}

// ---------------------------------------------------------------------------
// Launch
// ---------------------------------------------------------------------------
extern "C" void kernel_launch(void* const* d_in, const int* in_sizes, int n_in,
                              void* d_out, int out_size)
{
    const float* x           = (const float*)d_in[0];
    const float* ln1_g       = (const float*)d_in[1];
    const float* ln1_b       = (const float*)d_in[2];
    const float* w_attn      = (const float*)d_in[3];
    const float* b_attn      = (const float*)d_in[4];
    const float* w_attn_proj = (const float*)d_in[5];
    const float* b_attn_proj = (const float*)d_in[6];
    const float* ln2_g       = (const float*)d_in[7];
    const float* ln2_b       = (const float*)d_in[8];
    const float* w_fc        = (const float*)d_in[9];
    const float* b_fc        = (const float*)d_in[10];
    const float* w_mlp_proj  = (const float*)d_in[11];
    const float* b_mlp_proj  = (const float*)d_in[12];
    float* out = (float*)d_out;

    float *x1;
    __half *qkv, *h, *y, *h2, *u, *wq, *wp, *wf, *wm;
    cudaGetSymbolAddress((void**)&x1,  g_x1);
    cudaGetSymbolAddress((void**)&qkv, g_qkv);
    cudaGetSymbolAddress((void**)&h,   g_h);
    cudaGetSymbolAddress((void**)&y,   g_y);
    cudaGetSymbolAddress((void**)&h2,  g_h2);
    cudaGetSymbolAddress((void**)&u,   g_u);
    cudaGetSymbolAddress((void**)&wq,  g_wq);
    cudaGetSymbolAddress((void**)&wp,  g_wp);
    cudaGetSymbolAddress((void**)&wf,  g_wf);
    cudaGetSymbolAddress((void**)&wm,  g_wm);

    cudaFuncSetAttribute(attn_mma_kernel,
        cudaFuncAttributeMaxDynamicSharedMemorySize, (int)ATTN_SMEM2);
    cudaFuncSetAttribute(mm_kernel<1>, cudaFuncAttributeMaxDynamicSharedMemorySize, (int)MM_SMEM);
    cudaFuncSetAttribute(mm_kernel<2>, cudaFuncAttributeMaxDynamicSharedMemorySize, (int)MM_SMEM);
    cudaFuncSetAttribute(mm_kernel<3>, cudaFuncAttributeMaxDynamicSharedMemorySize, (int)MM_SMEM);
    cudaFuncSetAttribute(mm_kernel<4>, cudaFuncAttributeMaxDynamicSharedMemorySize, (int)MM_SMEM);

    // all weight transposes -> fp16 (one launch)
    tsplit_all<<<6912, 256>>>(w_attn, wq, w_attn_proj, wp, w_fc, wf, w_mlp_proj, wm);

    // 1. LN1 -> fp16
    ln_kernel<<<M_ROWS, 256>>>(x, ln1_g, ln1_b, h);
    // 2. qkv = h @ w_attn + b  -> fp16, Q cols pre-scaled by 1/8
    mm_kernel<4><<<dim3(C3_DIM / 128, M_ROWS / 128), 256, MM_SMEM>>>(
        h, wq, b_attn, nullptr, nullptr, qkv, M_ROWS, C3_DIM, C_DIM);
    // 3. attention (tensor-core flash) -> y fp16
    attn_mma_kernel<<<dim3(T_SEQ / 128, N_HEAD, 2), 256, ATTN_SMEM2>>>(qkv, y);
    // 4. x1 = x + y @ w_attn_proj + b
    mm_kernel<1><<<dim3(C_DIM / 128, M_ROWS / 128), 256, MM_SMEM>>>(
        y, wp, b_attn_proj, x, x1, nullptr, M_ROWS, C_DIM, C_DIM);
    // 5. LN2 -> fp16
    ln_kernel<<<M_ROWS, 256>>>(x1, ln2_g, ln2_b, h2);
    // 6. u = gelu(h2 @ w_fc + b) -> fp16
    mm_kernel<2><<<dim3(C4_DIM / 128, M_ROWS / 128), 256, MM_SMEM>>>(
        h2, wf, b_fc, nullptr, nullptr, u, M_ROWS, C4_DIM, C_DIM);
    // 7. out = x1 + u @ w_mlp_proj + b
    mm_kernel<3><<<dim3(C_DIM / 128, M_ROWS / 128), 256, MM_SMEM>>>(
        u, wm, b_mlp_proj, x1, out, nullptr, M_ROWS, C_DIM, C4_DIM);
}

// round 15
// speedup vs baseline: 2.5671x; 1.0658x over previous
#include <cuda_runtime.h>
#include <cuda_fp16.h>
#include <math.h>
#include <stdint.h>

// ---------------------------------------------------------------------------
// GPT-2 transformer block. GEMMs + attention on mma.sync fp16 single-term.
// 4-stage GEMM pipeline; persistent work-stealing attention with MUFU exp.
// B=2, T=2048, C=768, H=12, hd=64.  M = B*T = 4096.
// ---------------------------------------------------------------------------

#define M_ROWS 4096
#define C_DIM  768
#define C3_DIM 2304
#define C4_DIM 3072
#define N_HEAD 12
#define HD     64
#define T_SEQ  2048
#define NQT    (T_SEQ / 128)           // 16
#define NITEMS (NQT * N_HEAD * 2)      // 384

// ---------------- scratch (device globals) ----------------
__device__ float  g_x1 [M_ROWS * C_DIM];
__device__ __half g_qkv[M_ROWS * C3_DIM];
__device__ __half g_h  [M_ROWS * C_DIM];
__device__ __half g_y  [M_ROWS * C_DIM];
__device__ __half g_h2 [M_ROWS * C_DIM];
__device__ __half g_u  [M_ROWS * C4_DIM];
__device__ __half g_wq [C3_DIM * C_DIM];
__device__ __half g_wp [C_DIM * C_DIM];
__device__ __half g_wf [C4_DIM * C_DIM];
__device__ __half g_wm [C_DIM * C4_DIM];
__device__ int    g_ctr;

// ---------------- PTX helpers (base ISA only) ----------
__device__ __forceinline__ uint32_t smem_u32(const void* p) {
    uint32_t a;
    asm("{ .reg .u64 t; cvta.to.shared.u64 t, %1; cvt.u32.u64 %0, t; }"
        : "=r"(a) : "l"(p));
    return a;
}

#define CPA16(dst, src) \
    asm volatile("cp.async.cg.shared.global [%0], [%1], 16;" :: "r"(dst), "l"(src))
#define CP_COMMIT() asm volatile("cp.async.commit_group;" ::: "memory")
#define CP_WAIT2()  asm volatile("cp.async.wait_group 2;" ::: "memory")
#define CP_WAIT1()  asm volatile("cp.async.wait_group 1;" ::: "memory")
#define CP_WAIT0()  asm volatile("cp.async.wait_group 0;" ::: "memory")

#define LDSM_X4(r, addr)                                                       \
    asm volatile("ldmatrix.sync.aligned.m8n8.x4.shared.b16 {%0,%1,%2,%3}, [%4];" \
        : "=r"((r)[0]), "=r"((r)[1]), "=r"((r)[2]), "=r"((r)[3]) : "r"(addr))

#define LDSM_X4_T(r, addr)                                                     \
    asm volatile("ldmatrix.sync.aligned.m8n8.x4.trans.shared.b16 {%0,%1,%2,%3}, [%4];" \
        : "=r"((r)[0]), "=r"((r)[1]), "=r"((r)[2]), "=r"((r)[3]) : "r"(addr))

#define MMA_F16(d, a, b)                                                       \
    asm volatile("mma.sync.aligned.m16n8k16.row.col.f32.f16.f16.f32 "          \
        "{%0,%1,%2,%3}, {%4,%5,%6,%7}, {%8,%9}, {%0,%1,%2,%3};"                \
        : "+f"((d)[0]), "+f"((d)[1]), "+f"((d)[2]), "+f"((d)[3])               \
        : "r"((a)[0]), "r"((a)[1]), "r"((a)[2]), "r"((a)[3]),                  \
          "r"((b)[0]), "r"((b)[1]))

__device__ __forceinline__ float gelu_f(float v) {
    const float c = 0.7978845608028654f;
    return 0.5f * v * (1.0f + tanhf(c * (v + 0.044715f * v * v * v)));
}
__device__ __forceinline__ uint32_t packh2(float a, float b) {
    __half2 h = __floats2half2_rn(a, b);
    return *(uint32_t*)&h;
}

// ---------------------------------------------------------------------------
// mma.sync fp16 GEMM: D[M,N] = A[M,K] @ B[N,K]^T + epilogue
// 128x128 CTA tile, 8 warps each 32(M)x64(N), K-chunks of 32.
// 4-stage cp.async ring, ONE __syncthreads per iteration.
// EP: 1/3=bias+res->f32  2=bias+gelu->fp16  4=bias, cols<C_DIM x0.125 ->fp16
// ---------------------------------------------------------------------------
#define MMBUF 5120                    // halves per (A or B) buffer: 128*40
#define MM_SMEM (size_t)(8 * MMBUF * sizeof(__half))   // 81920 B

template <int EP>
__global__ __launch_bounds__(256, 2)
void mm_kernel(const __half* __restrict__ A, const __half* __restrict__ B,
               const float* __restrict__ bias, const float* __restrict__ res,
               float* __restrict__ outF, __half* __restrict__ outH,
               int M, int N, int K)
{
    extern __shared__ __half mmsm[];
    uint32_t base = smem_u32(mmsm);
    uint32_t sA[4], sB[4];
    #pragma unroll
    for (int i = 0; i < 4; i++) {
        sA[i] = base + i * MMBUF * 2;
        sB[i] = base + (4 + i) * MMBUF * 2;
    }

    int tid = threadIdx.x;
    int wid = tid >> 5, lane = tid & 31;
    int wm = wid & 3, wn = wid >> 2;
    int bm = blockIdx.y, bn = blockIdx.x;

    const int NIT = K / 32;

    auto load_chunk = [&](int it2, int b2) {
        int k0 = it2 * 32;
        #pragma unroll
        for (int i = 0; i < 2; i++) {
            int s = tid + i * 256;
            int r = s >> 2, c = s & 3;
            CPA16(sA[b2] + r * 80 + c * 16,
                  (const char*)(A + (size_t)(bm * 128 + r) * K + k0) + c * 16);
            CPA16(sB[b2] + r * 80 + c * 16,
                  (const char*)(B + (size_t)(bn * 128 + r) * K + k0) + c * 16);
        }
    };

    float acc[2][8][4];
    #pragma unroll
    for (int i = 0; i < 2; i++)
        #pragma unroll
        for (int j = 0; j < 8; j++)
            #pragma unroll
            for (int q = 0; q < 4; q++) acc[i][j][q] = 0.f;

    load_chunk(0, 0); CP_COMMIT();
    load_chunk(1, 1); CP_COMMIT();
    load_chunk(2, 2); CP_COMMIT();

    int mrow = (lane & 7) + ((lane >> 3) & 1) * 8;
    int kgrp = (lane >> 4) * 8;

    for (int it = 0; it < NIT; ++it) {
        int b = it & 3;
        if (it + 2 < NIT) CP_WAIT2();
        else if (it + 1 < NIT) CP_WAIT1();
        else CP_WAIT0();
        __syncthreads();                       // chunk it ready + iter it-1 reads done
        if (it + 3 < NIT) { load_chunk(it + 3, (it + 3) & 3); CP_COMMIT(); }

        #pragma unroll
        for (int ks = 0; ks < 2; ks++) {
            int kcol = ks * 16 + kgrp;
            uint32_t af[2][4], bf[4][4];
            #pragma unroll
            for (int mt = 0; mt < 2; mt++)
                LDSM_X4(af[mt], sA[b] + ((wm * 32 + mt * 16 + mrow) * 80 + kcol * 2));
            #pragma unroll
            for (int np = 0; np < 4; np++)
                LDSM_X4(bf[np], sB[b] + ((wn * 64 + np * 16 + mrow) * 80 + kcol * 2));
            #pragma unroll
            for (int mt = 0; mt < 2; mt++)
                #pragma unroll
                for (int nt = 0; nt < 8; nt++) {
                    uint32_t bb[2] = { bf[nt >> 1][nt & 1], bf[nt >> 1][(nt & 1) + 2] };
                    MMA_F16(acc[mt][nt], af[mt], bb);
                }
        }
    }

    #pragma unroll
    for (int mt = 0; mt < 2; mt++) {
        int gr0 = bm * 128 + wm * 32 + mt * 16 + (lane >> 2);
        #pragma unroll
        for (int nt = 0; nt < 8; nt++) {
            int gc = bn * 128 + wn * 64 + nt * 8 + (lane & 3) * 2;
            float2 bi = *(const float2*)(bias + gc);
            #pragma unroll
            for (int h = 0; h < 2; h++) {
                int gr = gr0 + h * 8;
                float v0 = acc[mt][nt][h * 2 + 0] + bi.x;
                float v1 = acc[mt][nt][h * 2 + 1] + bi.y;
                size_t o = (size_t)gr * N + gc;
                if (EP == 1 || EP == 3) {
                    float2 rr = *(const float2*)(res + o);
                    v0 += rr.x; v1 += rr.y;
                    float2 ov = {v0, v1};
                    *(float2*)(outF + o) = ov;
                } else {
                    if (EP == 2) { v0 = gelu_f(v0); v1 = gelu_f(v1); }
                    if (EP == 4 && gc < C_DIM) { v0 *= 0.125f; v1 *= 0.125f; }
                    __half2 hv = __floats2half2_rn(v0, v1);
                    *(__half2*)(outH + o) = hv;
                }
            }
        }
    }
}

// ---------------------------------------------------------------------------
// All 4 weight transposes (f32 [K,N] -> fp16 [N,K]) in ONE launch.
// ---------------------------------------------------------------------------
__global__ __launch_bounds__(256) void tsplit_all(
    const float* __restrict__ w0, __half* __restrict__ t0,
    const float* __restrict__ w1, __half* __restrict__ t1,
    const float* __restrict__ w2, __half* __restrict__ t2,
    const float* __restrict__ w3, __half* __restrict__ t3)
{
    int bid = blockIdx.x;
    const float* w; __half* th; int K, N, lb;
    if (bid < 1728)      { w = w0; th = t0; K = 768;  N = 2304; lb = bid; }
    else if (bid < 2304) { w = w1; th = t1; K = 768;  N = 768;  lb = bid - 1728; }
    else if (bid < 4608) { w = w2; th = t2; K = 768;  N = 3072; lb = bid - 2304; }
    else                 { w = w3; th = t3; K = 3072; N = 768;  lb = bid - 4608; }

    __shared__ float t[32][33];
    int nb = N >> 5;
    int n0 = (lb % nb) * 32, k0 = (lb / nb) * 32;
    int tx = threadIdx.x & 31, ty = threadIdx.x >> 5;
    #pragma unroll
    for (int j = 0; j < 4; j++) {
        int k = ty + j * 8;
        t[k][tx] = w[(size_t)(k0 + k) * N + n0 + tx];
    }
    __syncthreads();
    #pragma unroll
    for (int j = 0; j < 4; j++) {
        int nn = ty + j * 8;
        th[(size_t)(n0 + nn) * K + k0 + tx] = __float2half_rn(t[tx][nn]);
    }
}

// ---------------------------------------------------------------------------
// LayerNorm -> fp16
// ---------------------------------------------------------------------------
__global__ __launch_bounds__(256) void ln_kernel(
    const float* __restrict__ x, const float* __restrict__ g,
    const float* __restrict__ b, __half* __restrict__ oh)
{
    int row = blockIdx.x;
    int tid = threadIdx.x;
    const float* xr = x + (size_t)row * C_DIM;

    float v0 = xr[tid], v1 = xr[tid + 256], v2 = xr[tid + 512];
    float s = v0 + v1 + v2;
    float sq = v0 * v0 + v1 * v1 + v2 * v2;
    #pragma unroll
    for (int o = 16; o > 0; o >>= 1) {
        s  += __shfl_xor_sync(0xffffffffu, s,  o);
        sq += __shfl_xor_sync(0xffffffffu, sq, o);
    }
    __shared__ float ss[8], sqs[8];
    int wid = tid >> 5, lane = tid & 31;
    if (lane == 0) { ss[wid] = s; sqs[wid] = sq; }
    __syncthreads();
    s = 0.f; sq = 0.f;
    #pragma unroll
    for (int i = 0; i < 8; i++) { s += ss[i]; sq += sqs[i]; }

    float mu = s * (1.0f / C_DIM);
    float var = sq * (1.0f / C_DIM) - mu * mu;
    float inv = rsqrtf(var + 1e-5f);

    size_t base = (size_t)row * C_DIM;
    #pragma unroll
    for (int e = 0; e < 3; e++) {
        int idx = tid + e * 256;
        float val = ((e == 0 ? v0 : e == 1 ? v1 : v2) - mu) * inv * g[idx] + b[idx];
        oh[base + idx] = __float2half_rn(val);
    }
}

// ---------------------------------------------------------------------------
// Flash attention, persistent work-stealing. mma.sync fp16, 3-buffer K/V
// ring, MUFU exp (__expf). smem 72KB -> 2 CTAs/SM; grid 304 resident CTAs.
// Item i -> qt = NQT-1 - i/(24)  (heavy first), hb = i%24.
// ---------------------------------------------------------------------------
#define ASTR 72
#define QBUF (128 * ASTR)
#define KVB  (64 * ASTR)
#define ATTN_SMEM2 (size_t)((QBUF + 6 * KVB) * sizeof(__half))

__global__ __launch_bounds__(256, 2) void attn_mma_kernel(
    const __half* __restrict__ qkv,
    __half* __restrict__ y)
{
    extern __shared__ __half smh[];
    __shared__ int s_item;
    uint32_t sQ = smem_u32(smh);
    uint32_t sK[3], sV[3];
    #pragma unroll
    for (int i = 0; i < 3; i++) {
        sK[i] = sQ + (QBUF + 2 * i * KVB) * 2;
        sV[i] = sK[i] + KVB * 2;
    }

    int tid = threadIdx.x, wid = tid >> 5, lane = tid & 31;
    int mrow = (lane & 7) + ((lane >> 3) & 1) * 8;
    int kgrp = (lane >> 4) * 8;

    for (;;) {
        if (tid == 0) s_item = atomicAdd(&g_ctr, 1);
        __syncthreads();
        int item = s_item;
        if (item >= NITEMS) return;

        int qt = NQT - 1 - item / (N_HEAD * 2);   // heavy tiles first
        int hb = item % (N_HEAD * 2);
        int hh = hb % N_HEAD, bb = hb / N_HEAD;

        auto load_kv = [&](int kt, int b2) {
            #pragma unroll
            for (int i = 0; i < 4; i++) {
                int s = tid + i * 256;          // 0..1023
                int arr = s >> 9;               // 0=K 1=V
                int rem = s & 511;
                int r = rem >> 3, c = rem & 7;
                int colb = ((arr == 0) ? C_DIM : 2 * C_DIM) + hh * HD;
                const __half* src = qkv
                    + (size_t)(bb * T_SEQ + kt * 64 + r) * C3_DIM + colb + c * 8;
                CPA16((arr ? sV[b2] : sK[b2]) + (r * ASTR + c * 8) * 2, src);
            }
        };

        // group 0: Q tile (128 x 64 fp16)
        #pragma unroll
        for (int i = 0; i < 4; i++) {
            int s = tid + i * 256;              // 0..1023
            int r = s >> 3, c = s & 7;
            const __half* src = qkv
                + (size_t)(bb * T_SEQ + qt * 128 + r) * C3_DIM + hh * HD + c * 8;
            CPA16(sQ + (r * ASTR + c * 8) * 2, src);
        }
        CP_COMMIT();
        load_kv(0, 0); CP_COMMIT();             // group 1
        load_kv(1, 1); CP_COMMIT();             // group 2  (nkt >= 2 always)

        CP_WAIT2();                             // Q complete
        __syncthreads();

        uint32_t qf[4][4];
        #pragma unroll
        for (int kc = 0; kc < 4; kc++) {
            uint32_t aoff = ((wid * 16 + mrow) * ASTR + kc * 16 + kgrp) * 2;
            LDSM_X4(qf[kc], sQ + aoff);
        }

        float m0 = -1e30f, m1 = -1e30f, l0 = 0.f, l1 = 0.f;
        float oacc[8][4];
        #pragma unroll
        for (int i = 0; i < 8; i++)
            #pragma unroll
            for (int j = 0; j < 4; j++) oacc[i][j] = 0.f;

        int nkt = 2 * qt + 2;
        for (int kt = 0; kt < nkt; kt++) {
            int b = kt % 3;
            if (kt + 1 < nkt) CP_WAIT1(); else CP_WAIT0();
            __syncthreads();                    // kv_kt ready + prev-iter reads done
            if (kt + 2 < nkt) { load_kv(kt + 2, (kt + 2) % 3); CP_COMMIT(); }

            // ---- S = Q @ K^T (single fp16 term) ----
            float sacc[8][4];
            #pragma unroll
            for (int i = 0; i < 8; i++)
                #pragma unroll
                for (int j = 0; j < 4; j++) sacc[i][j] = 0.f;

            #pragma unroll
            for (int kc = 0; kc < 4; kc++) {
                #pragma unroll
                for (int ng = 0; ng < 4; ng++) {
                    uint32_t bh[4];
                    uint32_t boff = ((ng * 16 + mrow) * ASTR + kc * 16 + kgrp) * 2;
                    LDSM_X4(bh, sK[b] + boff);
                    #pragma unroll
                    for (int t = 0; t < 2; t++) {
                        uint32_t b0[2] = { bh[t], bh[t + 2] };
                        MMA_F16(sacc[ng * 2 + t], qf[kc], b0);
                    }
                }
            }

            // ---- causal mask ----
            int g0 = qt * 128 + wid * 16 + (lane >> 2);
            if (kt * 64 + 63 > qt * 128 + wid * 16) {
                #pragma unroll
                for (int nt = 0; nt < 8; nt++) {
                    int kc0 = kt * 64 + nt * 8 + (lane & 3) * 2;
                    if (kc0     > g0)     sacc[nt][0] = -1e30f;
                    if (kc0 + 1 > g0)     sacc[nt][1] = -1e30f;
                    if (kc0     > g0 + 8) sacc[nt][2] = -1e30f;
                    if (kc0 + 1 > g0 + 8) sacc[nt][3] = -1e30f;
                }
            }

            // ---- online softmax (MUFU exp; FMA pipe stays free for MMA-adjacent work) ----
            float mt0 = -1e30f, mt1 = -1e30f;
            #pragma unroll
            for (int nt = 0; nt < 8; nt++) {
                mt0 = fmaxf(mt0, fmaxf(sacc[nt][0], sacc[nt][1]));
                mt1 = fmaxf(mt1, fmaxf(sacc[nt][2], sacc[nt][3]));
            }
            mt0 = fmaxf(mt0, __shfl_xor_sync(0xffffffffu, mt0, 1));
            mt0 = fmaxf(mt0, __shfl_xor_sync(0xffffffffu, mt0, 2));
            mt1 = fmaxf(mt1, __shfl_xor_sync(0xffffffffu, mt1, 1));
            mt1 = fmaxf(mt1, __shfl_xor_sync(0xffffffffu, mt1, 2));

            float mn0 = fmaxf(m0, mt0), mn1 = fmaxf(m1, mt1);
            float c0 = __expf(m0 - mn0), c1 = __expf(m1 - mn1);
            m0 = mn0; m1 = mn1;

            float ps0 = 0.f, ps1 = 0.f;
            #pragma unroll
            for (int nt = 0; nt < 8; nt++) {
                sacc[nt][0] = __expf(sacc[nt][0] - m0);
                sacc[nt][1] = __expf(sacc[nt][1] - m0);
                sacc[nt][2] = __expf(sacc[nt][2] - m1);
                sacc[nt][3] = __expf(sacc[nt][3] - m1);
                ps0 += sacc[nt][0] + sacc[nt][1];
                ps1 += sacc[nt][2] + sacc[nt][3];
            }
            ps0 += __shfl_xor_sync(0xffffffffu, ps0, 1);
            ps0 += __shfl_xor_sync(0xffffffffu, ps0, 2);
            ps1 += __shfl_xor_sync(0xffffffffu, ps1, 1);
            ps1 += __shfl_xor_sync(0xffffffffu, ps1, 2);
            l0 = l0 * c0 + ps0;
            l1 = l1 * c1 + ps1;
            #pragma unroll
            for (int dt = 0; dt < 8; dt++) {
                oacc[dt][0] *= c0; oacc[dt][1] *= c0;
                oacc[dt][2] *= c1; oacc[dt][3] *= c1;
            }

            // ---- O += P @ V (single fp16 term), P frags in-register ----
            #pragma unroll
            for (int kc = 0; kc < 4; kc++) {
                uint32_t ah[4];
                ah[0] = packh2(sacc[2 * kc][0],     sacc[2 * kc][1]);
                ah[1] = packh2(sacc[2 * kc][2],     sacc[2 * kc][3]);
                ah[2] = packh2(sacc[2 * kc + 1][0], sacc[2 * kc + 1][1]);
                ah[3] = packh2(sacc[2 * kc + 1][2], sacc[2 * kc + 1][3]);
                #pragma unroll
                for (int ng = 0; ng < 4; ng++) {
                    uint32_t bv[4];
                    uint32_t voff = ((kc * 16 + ((lane >> 3) & 1) * 8 + (lane & 7)) * ASTR
                                     + ng * 16 + (lane >> 4) * 8) * 2;
                    LDSM_X4_T(bv, sV[b] + voff);
                    #pragma unroll
                    for (int t = 0; t < 2; t++) {
                        uint32_t b0[2] = { bv[2 * t], bv[2 * t + 1] };
                        MMA_F16(oacc[ng * 2 + t], ah, b0);
                    }
                }
            }
        }

        // ---- epilogue: normalize, store fp16 ----
        float i0 = 1.0f / l0, i1 = 1.0f / l1;
        int gr0 = qt * 128 + wid * 16 + (lane >> 2);
        #pragma unroll
        for (int dt = 0; dt < 8; dt++) {
            int col = hh * HD + dt * 8 + (lane & 3) * 2;
            size_t o0 = ((size_t)(bb * T_SEQ + gr0)) * C_DIM + col;
            size_t o1 = ((size_t)(bb * T_SEQ + gr0 + 8)) * C_DIM + col;
            *(__half2*)(y + o0) = __floats2half2_rn(oacc[dt][0] * i0, oacc[dt][1] * i0);
            *(__half2*)(y + o1) = __floats2half2_rn(oacc[dt][2] * i1, oacc[dt][3] * i1);
        }
        __syncthreads();   // protect s_item + smem before next item
    }
}

// ---------------------------------------------------------------------------
// Launch
// ---------------------------------------------------------------------------
extern "C" void kernel_launch(void* const* d_in, const int* in_sizes, int n_in,
                              void* d_out, int out_size)
{
    const float* x           = (const float*)d_in[0];
    const float* ln1_g       = (const float*)d_in[1];
    const float* ln1_b       = (const float*)d_in[2];
    const float* w_attn      = (const float*)d_in[3];
    const float* b_attn      = (const float*)d_in[4];
    const float* w_attn_proj = (const float*)d_in[5];
    const float* b_attn_proj = (const float*)d_in[6];
    const float* ln2_g       = (const float*)d_in[7];
    const float* ln2_b       = (const float*)d_in[8];
    const float* w_fc        = (const float*)d_in[9];
    const float* b_fc        = (const float*)d_in[10];
    const float* w_mlp_proj  = (const float*)d_in[11];
    const float* b_mlp_proj  = (const float*)d_in[12];
    float* out = (float*)d_out;

    float *x1;
    __half *qkv, *h, *y, *h2, *u, *wq, *wp, *wf, *wm;
    int *ctr;
    cudaGetSymbolAddress((void**)&x1,  g_x1);
    cudaGetSymbolAddress((void**)&qkv, g_qkv);
    cudaGetSymbolAddress((void**)&h,   g_h);
    cudaGetSymbolAddress((void**)&y,   g_y);
    cudaGetSymbolAddress((void**)&h2,  g_h2);
    cudaGetSymbolAddress((void**)&u,   g_u);
    cudaGetSymbolAddress((void**)&wq,  g_wq);
    cudaGetSymbolAddress((void**)&wp,  g_wp);
    cudaGetSymbolAddress((void**)&wf,  g_wf);
    cudaGetSymbolAddress((void**)&wm,  g_wm);
    cudaGetSymbolAddress((void**)&ctr, g_ctr);

    cudaFuncSetAttribute(attn_mma_kernel,
        cudaFuncAttributeMaxDynamicSharedMemorySize, (int)ATTN_SMEM2);
    cudaFuncSetAttribute(mm_kernel<1>, cudaFuncAttributeMaxDynamicSharedMemorySize, (int)MM_SMEM);
    cudaFuncSetAttribute(mm_kernel<2>, cudaFuncAttributeMaxDynamicSharedMemorySize, (int)MM_SMEM);
    cudaFuncSetAttribute(mm_kernel<3>, cudaFuncAttributeMaxDynamicSharedMemorySize, (int)MM_SMEM);
    cudaFuncSetAttribute(mm_kernel<4>, cudaFuncAttributeMaxDynamicSharedMemorySize, (int)MM_SMEM);

    // all weight transposes -> fp16 (one launch)
    tsplit_all<<<6912, 256>>>(w_attn, wq, w_attn_proj, wp, w_fc, wf, w_mlp_proj, wm);
    // reset work-stealing counter (captured as a memset node)
    cudaMemsetAsync(ctr, 0, sizeof(int));

    // 1. LN1 -> fp16
    ln_kernel<<<M_ROWS, 256>>>(x, ln1_g, ln1_b, h);
    // 2. qkv = h @ w_attn + b  -> fp16, Q cols pre-scaled by 1/8
    mm_kernel<4><<<dim3(C3_DIM / 128, M_ROWS / 128), 256, MM_SMEM>>>(
        h, wq, b_attn, nullptr, nullptr, qkv, M_ROWS, C3_DIM, C_DIM);
    // 3. attention (persistent, tensor-core flash) -> y fp16
    attn_mma_kernel<<<304, 256, ATTN_SMEM2>>>(qkv, y);
    // 4. x1 = x + y @ w_attn_proj + b
    mm_kernel<1><<<dim3(C_DIM / 128, M_ROWS / 128), 256, MM_SMEM>>>(
        y, wp, b_attn_proj, x, x1, nullptr, M_ROWS, C_DIM, C_DIM);
    // 5. LN2 -> fp16
    ln_kernel<<<M_ROWS, 256>>>(x1, ln2_g, ln2_b, h2);
    // 6. u = gelu(h2 @ w_fc + b) -> fp16
    mm_kernel<2><<<dim3(C4_DIM / 128, M_ROWS / 128), 256, MM_SMEM>>>(
        h2, wf, b_fc, nullptr, nullptr, u, M_ROWS, C4_DIM, C_DIM);
    // 7. out = x1 + u @ w_mlp_proj + b
    mm_kernel<3><<<dim3(C_DIM / 128, M_ROWS / 128), 256, MM_SMEM>>>(
        u, wm, b_mlp_proj, x1, out, nullptr, M_ROWS, C_DIM, C4_DIM);
}

// round 16
// speedup vs baseline: 2.8038x; 1.0922x over previous
#include <cuda_runtime.h>
#include <cuda_fp16.h>
#include <math.h>
#include <stdint.h>

// ---------------------------------------------------------------------------
// GPT-2 transformer block. GEMMs + attention on mma.sync fp16 single-term.
// GEMM: K-chunk 64, 3-stage cp.async ring, 1 barrier/iter, 2 CTAs/SM.
// Attention: persistent work-stealing, MUFU exp, 3-buffer K/V ring.
// B=2, T=2048, C=768, H=12, hd=64.  M = B*T = 4096.
// ---------------------------------------------------------------------------

#define M_ROWS 4096
#define C_DIM  768
#define C3_DIM 2304
#define C4_DIM 3072
#define N_HEAD 12
#define HD     64
#define T_SEQ  2048
#define NQT    (T_SEQ / 128)           // 16
#define NITEMS (NQT * N_HEAD * 2)      // 384

// ---------------- scratch (device globals) ----------------
__device__ float  g_x1 [M_ROWS * C_DIM];
__device__ __half g_qkv[M_ROWS * C3_DIM];
__device__ __half g_h  [M_ROWS * C_DIM];
__device__ __half g_y  [M_ROWS * C_DIM];
__device__ __half g_h2 [M_ROWS * C_DIM];
__device__ __half g_u  [M_ROWS * C4_DIM];
__device__ __half g_wq [C3_DIM * C_DIM];
__device__ __half g_wp [C_DIM * C_DIM];
__device__ __half g_wf [C4_DIM * C_DIM];
__device__ __half g_wm [C_DIM * C4_DIM];
__device__ int    g_ctr;

// ---------------- PTX helpers (base ISA only) ----------
__device__ __forceinline__ uint32_t smem_u32(const void* p) {
    uint32_t a;
    asm("{ .reg .u64 t; cvta.to.shared.u64 t, %1; cvt.u32.u64 %0, t; }"
        : "=r"(a) : "l"(p));
    return a;
}

#define CPA16(dst, src) \
    asm volatile("cp.async.cg.shared.global [%0], [%1], 16;" :: "r"(dst), "l"(src))
#define CP_COMMIT() asm volatile("cp.async.commit_group;" ::: "memory")
#define CP_WAIT2()  asm volatile("cp.async.wait_group 2;" ::: "memory")
#define CP_WAIT1()  asm volatile("cp.async.wait_group 1;" ::: "memory")
#define CP_WAIT0()  asm volatile("cp.async.wait_group 0;" ::: "memory")

#define LDSM_X4(r, addr)                                                       \
    asm volatile("ldmatrix.sync.aligned.m8n8.x4.shared.b16 {%0,%1,%2,%3}, [%4];" \
        : "=r"((r)[0]), "=r"((r)[1]), "=r"((r)[2]), "=r"((r)[3]) : "r"(addr))

#define LDSM_X4_T(r, addr)                                                     \
    asm volatile("ldmatrix.sync.aligned.m8n8.x4.trans.shared.b16 {%0,%1,%2,%3}, [%4];" \
        : "=r"((r)[0]), "=r"((r)[1]), "=r"((r)[2]), "=r"((r)[3]) : "r"(addr))

#define MMA_F16(d, a, b)                                                       \
    asm volatile("mma.sync.aligned.m16n8k16.row.col.f32.f16.f16.f32 "          \
        "{%0,%1,%2,%3}, {%4,%5,%6,%7}, {%8,%9}, {%0,%1,%2,%3};"                \
        : "+f"((d)[0]), "+f"((d)[1]), "+f"((d)[2]), "+f"((d)[3])               \
        : "r"((a)[0]), "r"((a)[1]), "r"((a)[2]), "r"((a)[3]),                  \
          "r"((b)[0]), "r"((b)[1]))

__device__ __forceinline__ float gelu_f(float v) {
    const float c = 0.7978845608028654f;
    return 0.5f * v * (1.0f + tanhf(c * (v + 0.044715f * v * v * v)));
}
__device__ __forceinline__ uint32_t packh2(float a, float b) {
    __half2 h = __floats2half2_rn(a, b);
    return *(uint32_t*)&h;
}

// ---------------------------------------------------------------------------
// mma.sync fp16 GEMM: D[M,N] = A[M,K] @ B[N,K]^T + epilogue
// 128x128 CTA tile, 8 warps each 32(M)x64(N), K-chunks of 64.
// 3-stage cp.async ring, ONE __syncthreads per iteration. smem 110.6KB.
// EP: 1/3=bias+res->f32  2=bias+gelu->fp16  4=bias, cols<C_DIM x0.125 ->fp16
// ---------------------------------------------------------------------------
#define MMSTR 72
#define MMBUF (128 * MMSTR)           // halves per (A or B) buffer
#define MM_SMEM (size_t)(6 * MMBUF * sizeof(__half))   // 110592 B

template <int EP>
__global__ __launch_bounds__(256, 2)
void mm_kernel(const __half* __restrict__ A, const __half* __restrict__ B,
               const float* __restrict__ bias, const float* __restrict__ res,
               float* __restrict__ outF, __half* __restrict__ outH,
               int M, int N, int K)
{
    extern __shared__ __half mmsm[];
    uint32_t base = smem_u32(mmsm);
    uint32_t sA[3], sB[3];
    #pragma unroll
    for (int i = 0; i < 3; i++) {
        sA[i] = base + i * MMBUF * 2;
        sB[i] = base + (3 + i) * MMBUF * 2;
    }

    int tid = threadIdx.x;
    int wid = tid >> 5, lane = tid & 31;
    int wm = wid & 3, wn = wid >> 2;
    int bm = blockIdx.y, bn = blockIdx.x;

    const int NIT = K / 64;

    auto load_chunk = [&](int it2, int b2) {
        int k0 = it2 * 64;
        #pragma unroll
        for (int i = 0; i < 4; i++) {
            int s = tid + i * 256;           // 0..1023
            int r = s >> 3, c = s & 7;       // row 0..127, 16B col 0..7
            CPA16(sA[b2] + (r * MMSTR + c * 8) * 2,
                  (const char*)(A + (size_t)(bm * 128 + r) * K + k0) + c * 16);
            CPA16(sB[b2] + (r * MMSTR + c * 8) * 2,
                  (const char*)(B + (size_t)(bn * 128 + r) * K + k0) + c * 16);
        }
    };

    float acc[2][8][4];
    #pragma unroll
    for (int i = 0; i < 2; i++)
        #pragma unroll
        for (int j = 0; j < 8; j++)
            #pragma unroll
            for (int q = 0; q < 4; q++) acc[i][j][q] = 0.f;

    load_chunk(0, 0); CP_COMMIT();
    load_chunk(1, 1); CP_COMMIT();

    int mrow = (lane & 7) + ((lane >> 3) & 1) * 8;
    int kgrp = (lane >> 4) * 8;

    for (int it = 0; it < NIT; ++it) {
        int b = it % 3;
        if (it + 1 < NIT) CP_WAIT1(); else CP_WAIT0();
        __syncthreads();                       // chunk it ready + iter it-1 reads done
        if (it + 2 < NIT) { load_chunk(it + 2, (it + 2) % 3); CP_COMMIT(); }

        #pragma unroll
        for (int ks = 0; ks < 4; ks++) {
            int kcol = ks * 16 + kgrp;
            uint32_t af[2][4], bf[4][4];
            #pragma unroll
            for (int mt = 0; mt < 2; mt++)
                LDSM_X4(af[mt], sA[b] + ((wm * 32 + mt * 16 + mrow) * MMSTR + kcol) * 2);
            #pragma unroll
            for (int np = 0; np < 4; np++)
                LDSM_X4(bf[np], sB[b] + ((wn * 64 + np * 16 + mrow) * MMSTR + kcol) * 2);
            #pragma unroll
            for (int mt = 0; mt < 2; mt++)
                #pragma unroll
                for (int nt = 0; nt < 8; nt++) {
                    uint32_t bb[2] = { bf[nt >> 1][nt & 1], bf[nt >> 1][(nt & 1) + 2] };
                    MMA_F16(acc[mt][nt], af[mt], bb);
                }
        }
    }

    #pragma unroll
    for (int mt = 0; mt < 2; mt++) {
        int gr0 = bm * 128 + wm * 32 + mt * 16 + (lane >> 2);
        #pragma unroll
        for (int nt = 0; nt < 8; nt++) {
            int gc = bn * 128 + wn * 64 + nt * 8 + (lane & 3) * 2;
            float2 bi = *(const float2*)(bias + gc);
            #pragma unroll
            for (int h = 0; h < 2; h++) {
                int gr = gr0 + h * 8;
                float v0 = acc[mt][nt][h * 2 + 0] + bi.x;
                float v1 = acc[mt][nt][h * 2 + 1] + bi.y;
                size_t o = (size_t)gr * N + gc;
                if (EP == 1 || EP == 3) {
                    float2 rr = *(const float2*)(res + o);
                    v0 += rr.x; v1 += rr.y;
                    float2 ov = {v0, v1};
                    *(float2*)(outF + o) = ov;
                } else {
                    if (EP == 2) { v0 = gelu_f(v0); v1 = gelu_f(v1); }
                    if (EP == 4 && gc < C_DIM) { v0 *= 0.125f; v1 *= 0.125f; }
                    __half2 hv = __floats2half2_rn(v0, v1);
                    *(__half2*)(outH + o) = hv;
                }
            }
        }
    }
}

// ---------------------------------------------------------------------------
// LayerNorm row body (shared by prep kernel and LN2 kernel)
// ---------------------------------------------------------------------------
__device__ __forceinline__ void ln_row_body(
    const float* __restrict__ x, const float* __restrict__ g,
    const float* __restrict__ b, __half* __restrict__ oh, int row, int tid)
{
    const float* xr = x + (size_t)row * C_DIM;
    float v0 = xr[tid], v1 = xr[tid + 256], v2 = xr[tid + 512];
    float s = v0 + v1 + v2;
    float sq = v0 * v0 + v1 * v1 + v2 * v2;
    #pragma unroll
    for (int o = 16; o > 0; o >>= 1) {
        s  += __shfl_xor_sync(0xffffffffu, s,  o);
        sq += __shfl_xor_sync(0xffffffffu, sq, o);
    }
    __shared__ float ss[8], sqs[8];
    int wid = tid >> 5, lane = tid & 31;
    if (lane == 0) { ss[wid] = s; sqs[wid] = sq; }
    __syncthreads();
    s = 0.f; sq = 0.f;
    #pragma unroll
    for (int i = 0; i < 8; i++) { s += ss[i]; sq += sqs[i]; }

    float mu = s * (1.0f / C_DIM);
    float var = sq * (1.0f / C_DIM) - mu * mu;
    float inv = rsqrtf(var + 1e-5f);

    size_t base = (size_t)row * C_DIM;
    #pragma unroll
    for (int e = 0; e < 3; e++) {
        int idx = tid + e * 256;
        float val = ((e == 0 ? v0 : e == 1 ? v1 : v2) - mu) * inv * g[idx] + b[idx];
        oh[base + idx] = __float2half_rn(val);
    }
}

// ---------------------------------------------------------------------------
// Prep kernel: 4 weight transposes + LN1 + work counter reset, one launch.
// Blocks 0..6911 transpose; 6912..11007 LN1 rows.
// ---------------------------------------------------------------------------
__global__ __launch_bounds__(256) void prep_kernel(
    const float* __restrict__ w0, __half* __restrict__ t0,
    const float* __restrict__ w1, __half* __restrict__ t1,
    const float* __restrict__ w2, __half* __restrict__ t2,
    const float* __restrict__ w3, __half* __restrict__ t3,
    const float* __restrict__ x, const float* __restrict__ ln1_g,
    const float* __restrict__ ln1_b, __half* __restrict__ h)
{
    int bid = blockIdx.x;
    if (bid == 0 && threadIdx.x == 0) g_ctr = 0;

    if (bid >= 6912) {
        ln_row_body(x, ln1_g, ln1_b, h, bid - 6912, threadIdx.x);
        return;
    }

    const float* w; __half* th; int K, N, lb;
    if (bid < 1728)      { w = w0; th = t0; K = 768;  N = 2304; lb = bid; }
    else if (bid < 2304) { w = w1; th = t1; K = 768;  N = 768;  lb = bid - 1728; }
    else if (bid < 4608) { w = w2; th = t2; K = 768;  N = 3072; lb = bid - 2304; }
    else                 { w = w3; th = t3; K = 3072; N = 768;  lb = bid - 4608; }

    __shared__ float t[32][33];
    int nb = N >> 5;
    int n0 = (lb % nb) * 32, k0 = (lb / nb) * 32;
    int tx = threadIdx.x & 31, ty = threadIdx.x >> 5;
    #pragma unroll
    for (int j = 0; j < 4; j++) {
        int k = ty + j * 8;
        t[k][tx] = w[(size_t)(k0 + k) * N + n0 + tx];
    }
    __syncthreads();
    #pragma unroll
    for (int j = 0; j < 4; j++) {
        int nn = ty + j * 8;
        th[(size_t)(n0 + nn) * K + k0 + tx] = __float2half_rn(t[tx][nn]);
    }
}

// ---------------------------------------------------------------------------
// LayerNorm 2 -> fp16
// ---------------------------------------------------------------------------
__global__ __launch_bounds__(256) void ln_kernel(
    const float* __restrict__ x, const float* __restrict__ g,
    const float* __restrict__ b, __half* __restrict__ oh)
{
    ln_row_body(x, g, b, oh, blockIdx.x, threadIdx.x);
}

// ---------------------------------------------------------------------------
// Flash attention, persistent work-stealing. mma.sync fp16, 3-buffer K/V
// ring, MUFU exp (__expf). smem 72KB -> 2 CTAs/SM; grid 304 resident CTAs.
// ---------------------------------------------------------------------------
#define ASTR 72
#define QBUF (128 * ASTR)
#define KVB  (64 * ASTR)
#define ATTN_SMEM2 (size_t)((QBUF + 6 * KVB) * sizeof(__half))

__global__ __launch_bounds__(256, 2) void attn_mma_kernel(
    const __half* __restrict__ qkv,
    __half* __restrict__ y)
{
    extern __shared__ __half smh[];
    __shared__ int s_item;
    uint32_t sQ = smem_u32(smh);
    uint32_t sK[3], sV[3];
    #pragma unroll
    for (int i = 0; i < 3; i++) {
        sK[i] = sQ + (QBUF + 2 * i * KVB) * 2;
        sV[i] = sK[i] + KVB * 2;
    }

    int tid = threadIdx.x, wid = tid >> 5, lane = tid & 31;
    int mrow = (lane & 7) + ((lane >> 3) & 1) * 8;
    int kgrp = (lane >> 4) * 8;

    for (;;) {
        if (tid == 0) s_item = atomicAdd(&g_ctr, 1);
        __syncthreads();
        int item = s_item;
        if (item >= NITEMS) return;

        int qt = NQT - 1 - item / (N_HEAD * 2);   // heavy tiles first
        int hb = item % (N_HEAD * 2);
        int hh = hb % N_HEAD, bb = hb / N_HEAD;

        auto load_kv = [&](int kt, int b2) {
            #pragma unroll
            for (int i = 0; i < 4; i++) {
                int s = tid + i * 256;          // 0..1023
                int arr = s >> 9;               // 0=K 1=V
                int rem = s & 511;
                int r = rem >> 3, c = rem & 7;
                int colb = ((arr == 0) ? C_DIM : 2 * C_DIM) + hh * HD;
                const __half* src = qkv
                    + (size_t)(bb * T_SEQ + kt * 64 + r) * C3_DIM + colb + c * 8;
                CPA16((arr ? sV[b2] : sK[b2]) + (r * ASTR + c * 8) * 2, src);
            }
        };

        // group 0: Q tile (128 x 64 fp16)
        #pragma unroll
        for (int i = 0; i < 4; i++) {
            int s = tid + i * 256;              // 0..1023
            int r = s >> 3, c = s & 7;
            const __half* src = qkv
                + (size_t)(bb * T_SEQ + qt * 128 + r) * C3_DIM + hh * HD + c * 8;
            CPA16(sQ + (r * ASTR + c * 8) * 2, src);
        }
        CP_COMMIT();
        load_kv(0, 0); CP_COMMIT();             // group 1
        load_kv(1, 1); CP_COMMIT();             // group 2  (nkt >= 2 always)

        CP_WAIT2();                             // Q complete
        __syncthreads();

        uint32_t qf[4][4];
        #pragma unroll
        for (int kc = 0; kc < 4; kc++) {
            uint32_t aoff = ((wid * 16 + mrow) * ASTR + kc * 16 + kgrp) * 2;
            LDSM_X4(qf[kc], sQ + aoff);
        }

        float m0 = -1e30f, m1 = -1e30f, l0 = 0.f, l1 = 0.f;
        float oacc[8][4];
        #pragma unroll
        for (int i = 0; i < 8; i++)
            #pragma unroll
            for (int j = 0; j < 4; j++) oacc[i][j] = 0.f;

        int nkt = 2 * qt + 2;
        for (int kt = 0; kt < nkt; kt++) {
            int b = kt % 3;
            if (kt + 1 < nkt) CP_WAIT1(); else CP_WAIT0();
            __syncthreads();                    // kv_kt ready + prev-iter reads done
            if (kt + 2 < nkt) { load_kv(kt + 2, (kt + 2) % 3); CP_COMMIT(); }

            // ---- S = Q @ K^T (single fp16 term) ----
            float sacc[8][4];
            #pragma unroll
            for (int i = 0; i < 8; i++)
                #pragma unroll
                for (int j = 0; j < 4; j++) sacc[i][j] = 0.f;

            #pragma unroll
            for (int kc = 0; kc < 4; kc++) {
                #pragma unroll
                for (int ng = 0; ng < 4; ng++) {
                    uint32_t bh[4];
                    uint32_t boff = ((ng * 16 + mrow) * ASTR + kc * 16 + kgrp) * 2;
                    LDSM_X4(bh, sK[b] + boff);
                    #pragma unroll
                    for (int t = 0; t < 2; t++) {
                        uint32_t b0[2] = { bh[t], bh[t + 2] };
                        MMA_F16(sacc[ng * 2 + t], qf[kc], b0);
                    }
                }
            }

            // ---- causal mask ----
            int g0 = qt * 128 + wid * 16 + (lane >> 2);
            if (kt * 64 + 63 > qt * 128 + wid * 16) {
                #pragma unroll
                for (int nt = 0; nt < 8; nt++) {
                    int kc0 = kt * 64 + nt * 8 + (lane & 3) * 2;
                    if (kc0     > g0)     sacc[nt][0] = -1e30f;
                    if (kc0 + 1 > g0)     sacc[nt][1] = -1e30f;
                    if (kc0     > g0 + 8) sacc[nt][2] = -1e30f;
                    if (kc0 + 1 > g0 + 8) sacc[nt][3] = -1e30f;
                }
            }

            // ---- online softmax (MUFU exp) ----
            float mt0 = -1e30f, mt1 = -1e30f;
            #pragma unroll
            for (int nt = 0; nt < 8; nt++) {
                mt0 = fmaxf(mt0, fmaxf(sacc[nt][0], sacc[nt][1]));
                mt1 = fmaxf(mt1, fmaxf(sacc[nt][2], sacc[nt][3]));
            }
            mt0 = fmaxf(mt0, __shfl_xor_sync(0xffffffffu, mt0, 1));
            mt0 = fmaxf(mt0, __shfl_xor_sync(0xffffffffu, mt0, 2));
            mt1 = fmaxf(mt1, __shfl_xor_sync(0xffffffffu, mt1, 1));
            mt1 = fmaxf(mt1, __shfl_xor_sync(0xffffffffu, mt1, 2));

            float mn0 = fmaxf(m0, mt0), mn1 = fmaxf(m1, mt1);
            float c0 = __expf(m0 - mn0), c1 = __expf(m1 - mn1);
            m0 = mn0; m1 = mn1;

            float ps0 = 0.f, ps1 = 0.f;
            #pragma unroll
            for (int nt = 0; nt < 8; nt++) {
                sacc[nt][0] = __expf(sacc[nt][0] - m0);
                sacc[nt][1] = __expf(sacc[nt][1] - m0);
                sacc[nt][2] = __expf(sacc[nt][2] - m1);
                sacc[nt][3] = __expf(sacc[nt][3] - m1);
                ps0 += sacc[nt][0] + sacc[nt][1];
                ps1 += sacc[nt][2] + sacc[nt][3];
            }
            ps0 += __shfl_xor_sync(0xffffffffu, ps0, 1);
            ps0 += __shfl_xor_sync(0xffffffffu, ps0, 2);
            ps1 += __shfl_xor_sync(0xffffffffu, ps1, 1);
            ps1 += __shfl_xor_sync(0xffffffffu, ps1, 2);
            l0 = l0 * c0 + ps0;
            l1 = l1 * c1 + ps1;
            #pragma unroll
            for (int dt = 0; dt < 8; dt++) {
                oacc[dt][0] *= c0; oacc[dt][1] *= c0;
                oacc[dt][2] *= c1; oacc[dt][3] *= c1;
            }

            // ---- O += P @ V (single fp16 term), P frags in-register ----
            #pragma unroll
            for (int kc = 0; kc < 4; kc++) {
                uint32_t ah[4];
                ah[0] = packh2(sacc[2 * kc][0],     sacc[2 * kc][1]);
                ah[1] = packh2(sacc[2 * kc][2],     sacc[2 * kc][3]);
                ah[2] = packh2(sacc[2 * kc + 1][0], sacc[2 * kc + 1][1]);
                ah[3] = packh2(sacc[2 * kc + 1][2], sacc[2 * kc + 1][3]);
                #pragma unroll
                for (int ng = 0; ng < 4; ng++) {
                    uint32_t bv[4];
                    uint32_t voff = ((kc * 16 + ((lane >> 3) & 1) * 8 + (lane & 7)) * ASTR
                                     + ng * 16 + (lane >> 4) * 8) * 2;
                    LDSM_X4_T(bv, sV[b] + voff);
                    #pragma unroll
                    for (int t = 0; t < 2; t++) {
                        uint32_t b0[2] = { bv[2 * t], bv[2 * t + 1] };
                        MMA_F16(oacc[ng * 2 + t], ah, b0);
                    }
                }
            }
        }

        // ---- epilogue: normalize, store fp16 ----
        float i0 = 1.0f / l0, i1 = 1.0f / l1;
        int gr0 = qt * 128 + wid * 16 + (lane >> 2);
        #pragma unroll
        for (int dt = 0; dt < 8; dt++) {
            int col = hh * HD + dt * 8 + (lane & 3) * 2;
            size_t o0 = ((size_t)(bb * T_SEQ + gr0)) * C_DIM + col;
            size_t o1 = ((size_t)(bb * T_SEQ + gr0 + 8)) * C_DIM + col;
            *(__half2*)(y + o0) = __floats2half2_rn(oacc[dt][0] * i0, oacc[dt][1] * i0);
            *(__half2*)(y + o1) = __floats2half2_rn(oacc[dt][2] * i1, oacc[dt][3] * i1);
        }
        __syncthreads();   // protect s_item + smem before next item
    }
}

// ---------------------------------------------------------------------------
// Launch
// ---------------------------------------------------------------------------
extern "C" void kernel_launch(void* const* d_in, const int* in_sizes, int n_in,
                              void* d_out, int out_size)
{
    const float* x           = (const float*)d_in[0];
    const float* ln1_g       = (const float*)d_in[1];
    const float* ln1_b       = (const float*)d_in[2];
    const float* w_attn      = (const float*)d_in[3];
    const float* b_attn      = (const float*)d_in[4];
    const float* w_attn_proj = (const float*)d_in[5];
    const float* b_attn_proj = (const float*)d_in[6];
    const float* ln2_g       = (const float*)d_in[7];
    const float* ln2_b       = (const float*)d_in[8];
    const float* w_fc        = (const float*)d_in[9];
    const float* b_fc        = (const float*)d_in[10];
    const float* w_mlp_proj  = (const float*)d_in[11];
    const float* b_mlp_proj  = (const float*)d_in[12];
    float* out = (float*)d_out;

    float *x1;
    __half *qkv, *h, *y, *h2, *u, *wq, *wp, *wf, *wm;
    cudaGetSymbolAddress((void**)&x1,  g_x1);
    cudaGetSymbolAddress((void**)&qkv, g_qkv);
    cudaGetSymbolAddress((void**)&h,   g_h);
    cudaGetSymbolAddress((void**)&y,   g_y);
    cudaGetSymbolAddress((void**)&h2,  g_h2);
    cudaGetSymbolAddress((void**)&u,   g_u);
    cudaGetSymbolAddress((void**)&wq,  g_wq);
    cudaGetSymbolAddress((void**)&wp,  g_wp);
    cudaGetSymbolAddress((void**)&wf,  g_wf);
    cudaGetSymbolAddress((void**)&wm,  g_wm);

    cudaFuncSetAttribute(attn_mma_kernel,
        cudaFuncAttributeMaxDynamicSharedMemorySize, (int)ATTN_SMEM2);
    cudaFuncSetAttribute(mm_kernel<1>, cudaFuncAttributeMaxDynamicSharedMemorySize, (int)MM_SMEM);
    cudaFuncSetAttribute(mm_kernel<2>, cudaFuncAttributeMaxDynamicSharedMemorySize, (int)MM_SMEM);
    cudaFuncSetAttribute(mm_kernel<3>, cudaFuncAttributeMaxDynamicSharedMemorySize, (int)MM_SMEM);
    cudaFuncSetAttribute(mm_kernel<4>, cudaFuncAttributeMaxDynamicSharedMemorySize, (int)MM_SMEM);

    // prep: weight transposes + LN1 + counter reset (one launch)
    prep_kernel<<<11008, 256>>>(w_attn, wq, w_attn_proj, wp, w_fc, wf,
                                w_mlp_proj, wm, x, ln1_g, ln1_b, h);

    // 2. qkv = h @ w_attn + b  -> fp16, Q cols pre-scaled by 1/8
    mm_kernel<4><<<dim3(C3_DIM / 128, M_ROWS / 128), 256, MM_SMEM>>>(
        h, wq, b_attn, nullptr, nullptr, qkv, M_ROWS, C3_DIM, C_DIM);
    // 3. attention (persistent, tensor-core flash) -> y fp16
    attn_mma_kernel<<<304, 256, ATTN_SMEM2>>>(qkv, y);
    // 4. x1 = x + y @ w_attn_proj + b
    mm_kernel<1><<<dim3(C_DIM / 128, M_ROWS / 128), 256, MM_SMEM>>>(
        y, wp, b_attn_proj, x, x1, nullptr, M_ROWS, C_DIM, C_DIM);
    // 5. LN2 -> fp16
    ln_kernel<<<M_ROWS, 256>>>(x1, ln2_g, ln2_b, h2);
    // 6. u = gelu(h2 @ w_fc + b) -> fp16
    mm_kernel<2><<<dim3(C4_DIM / 128, M_ROWS / 128), 256, MM_SMEM>>>(
        h2, wf, b_fc, nullptr, nullptr, u, M_ROWS, C4_DIM, C_DIM);
    // 7. out = x1 + u @ w_mlp_proj + b
    mm_kernel<3><<<dim3(C_DIM / 128, M_ROWS / 128), 256, MM_SMEM>>>(
        u, wm, b_mlp_proj, x1, out, nullptr, M_ROWS, C_DIM, C4_DIM);
}